// round 14
// baseline (speedup 1.0000x reference)
#include <cuda_runtime.h>
#include <cuda_fp16.h>
#include <math.h>
#include <stdint.h>

// ---------------- problem constants ----------------
#define BATCH 16
#define NPTS  4096
#define DFEAT 64
#define SPTS  1024
#define NSAMP 32
#define CH0   67
#define CH1   64
#define CH2   128
#define CH3   256
#define MTOT  (BATCH*SPTS*NSAMP)   // 524288
#define MBLK  (MTOT/128)           // 4096
#define RAD2  0.04f
#define BNEPS 1e-5f

typedef unsigned long long ull;

// ---------------- device scratch ----------------
__device__ float    g_G[(size_t)BATCH*NPTS*CH1];
__device__ uint32_t g_y1[(size_t)MTOT*CH1/2];      // fp16 pairs
__device__ uint32_t g_y2[(size_t)MTOT*CH2/2];      // fp16 pairs
__device__ int   g_gidx[BATCH*SPTS*NSAMP];
__device__ float g_part[2*(size_t)MBLK*CH3];       // transposed [n][MBLK]
__device__ float g_scale[CH3];
__device__ float g_shift[CH3];
__device__ float g_gmax[(size_t)BATCH*SPTS*CH3];
__device__ float g_gmin[(size_t)BATCH*SPTS*CH3];
__device__ __half g_bh0[64*64],   g_bl0[64*64];
__device__ __half g_bh1[64*128],  g_bl1[64*128];
__device__ __half g_bh2[128*256], g_bl2[128*256];

// ---------------- helpers ----------------
__device__ __forceinline__ uint32_t smem_u32(const void* p) {
    uint32_t a;
    asm("{ .reg .u64 t; cvta.to.shared.u64 t, %1; cvt.u32.u64 %0, t; }" : "=r"(a) : "l"(p));
    return a;
}
__device__ __forceinline__ void ldsm4(uint32_t* r, uint32_t a) {
    asm volatile("ldmatrix.sync.aligned.m8n8.x4.shared.b16 {%0,%1,%2,%3}, [%4];"
                 : "=r"(r[0]), "=r"(r[1]), "=r"(r[2]), "=r"(r[3]) : "r"(a));
}
__device__ __forceinline__ void ldsm4t(uint32_t* r, uint32_t a) {
    asm volatile("ldmatrix.sync.aligned.m8n8.x4.trans.shared.b16 {%0,%1,%2,%3}, [%4];"
                 : "=r"(r[0]), "=r"(r[1]), "=r"(r[2]), "=r"(r[3]) : "r"(a));
}
__device__ __forceinline__ void mma_f16(float* c, const uint32_t* a, uint32_t b0, uint32_t b1) {
    asm volatile(
        "mma.sync.aligned.m16n8k16.row.col.f32.f16.f16.f32 "
        "{%0,%1,%2,%3}, {%4,%5,%6,%7}, {%8,%9}, {%0,%1,%2,%3};"
        : "+f"(c[0]), "+f"(c[1]), "+f"(c[2]), "+f"(c[3])
        : "r"(a[0]), "r"(a[1]), "r"(a[2]), "r"(a[3]), "r"(b0), "r"(b1));
}
__device__ __forceinline__ uint32_t packh2(float v0, float v1) {
    __half2 h = __floats2half2_rn(v0, v1);
    return *(uint32_t*)&h;
}

// ---------------- FPS (512 threads, packed f32x2, REDUX tails) ----------------
__global__ __launch_bounds__(512) void fps_kernel(const float* __restrict__ xyz,
                                                  float* __restrict__ new_xyz)
{
    __shared__ float sx[NPTS], sy[NPTS], sz[NPTS];
    __shared__ unsigned s_val[2][16], s_low[2][16];
    const int b = blockIdx.x, tid = threadIdx.x;
    const int lane = tid & 31, wid = tid >> 5;
    const float* X = xyz + (size_t)b * NPTS * 3;

    ull pxp[4], pyp[4], pzp[4];
    float dist[8];
#pragma unroll
    for (int t = 0; t < 8; t++) dist[t] = 1e10f;
#pragma unroll
    for (int t = 0; t < 4; t++) {
        const int j0 = tid + (2*t) * 512, j1 = tid + (2*t+1) * 512;
        float x0 = X[3*j0], y0 = X[3*j0+1], z0 = X[3*j0+2];
        float x1 = X[3*j1], y1 = X[3*j1+1], z1 = X[3*j1+2];
        sx[j0] = x0; sy[j0] = y0; sz[j0] = z0;
        sx[j1] = x1; sy[j1] = y1; sz[j1] = z1;
        asm("mov.b64 %0, {%1,%2};" : "=l"(pxp[t]) : "f"(x0), "f"(x1));
        asm("mov.b64 %0, {%1,%2};" : "=l"(pyp[t]) : "f"(y0), "f"(y1));
        asm("mov.b64 %0, {%1,%2};" : "=l"(pzp[t]) : "f"(z0), "f"(z1));
    }
    __syncthreads();

    int far = 0;
    for (int i = 0; i < SPTS; i++) {
        const float cx = sx[far], cy = sy[far], cz = sz[far];
        if (tid == 0) {
            float* o = new_xyz + ((size_t)b * SPTS + i) * 3;
            o[0] = cx; o[1] = cy; o[2] = cz;
        }
        if (i == SPTS - 1) break;

        const float mx = -cx, my = -cy, mz = -cz;
        ull ncx, ncy, ncz;
        asm("mov.b64 %0, {%1,%1};" : "=l"(ncx) : "f"(mx));
        asm("mov.b64 %0, {%1,%1};" : "=l"(ncy) : "f"(my));
        asm("mov.b64 %0, {%1,%1};" : "=l"(ncz) : "f"(mz));

        float bv = -1.0f; int bi = 0;
#pragma unroll
        for (int t = 0; t < 4; t++) {
            ull dx, dy, dz, dd;
            asm("add.rn.f32x2 %0, %1, %2;" : "=l"(dx) : "l"(pxp[t]), "l"(ncx));
            asm("add.rn.f32x2 %0, %1, %2;" : "=l"(dy) : "l"(pyp[t]), "l"(ncy));
            asm("add.rn.f32x2 %0, %1, %2;" : "=l"(dz) : "l"(pzp[t]), "l"(ncz));
            asm("mul.rn.f32x2 %0, %1, %2;" : "=l"(dd) : "l"(dx), "l"(dx));
            asm("fma.rn.f32x2 %0, %1, %2, %3;" : "=l"(dd) : "l"(dy), "l"(dy), "l"(dd));
            asm("fma.rn.f32x2 %0, %1, %2, %3;" : "=l"(dd) : "l"(dz), "l"(dz), "l"(dd));
            float d0, d1;
            asm("mov.b64 {%0,%1}, %2;" : "=f"(d0), "=f"(d1) : "l"(dd));
            const float nd0 = fminf(dist[2*t],   d0);
            const float nd1 = fminf(dist[2*t+1], d1);
            dist[2*t]   = nd0;
            dist[2*t+1] = nd1;
            if (nd0 > bv) { bv = nd0; bi = tid + (2*t)   * 512; }
            if (nd1 > bv) { bv = nd1; bi = tid + (2*t+1) * 512; }
        }
        const unsigned vb = __float_as_uint(bv);
        const unsigned m  = __reduce_max_sync(0xffffffffu, vb);
        const unsigned lw = __reduce_max_sync(0xffffffffu,
                                              (vb == m) ? (0xFFFFu - (unsigned)bi) : 0u);
        const int buf = i & 1;
        if (lane == 0) { s_val[buf][wid] = m; s_low[buf][wid] = lw; }
        __syncthreads();

        const unsigned v2 = s_val[buf][lane & 15];
        const unsigned l2 = s_low[buf][lane & 15];
        const unsigned M  = __reduce_max_sync(0xffffffffu, v2);
        const unsigned LW = __reduce_max_sync(0xffffffffu, (v2 == M) ? l2 : 0u);
        far = 0xFFFF - (int)LW;
    }
}

// ---------------- weight prep ----------------
__global__ __launch_bounds__(256) void prep_kernel(const float* __restrict__ W, int K, int N,
                                                   int KPAD, int KOFF,
                                                   __half* __restrict__ bh,
                                                   __half* __restrict__ bl)
{
    int i = blockIdx.x * 256 + threadIdx.x;
    if (i >= N * KPAD) return;
    int k = i / N, n = i - k * N;
    float v = (k < K) ? W[(size_t)(k + KOFF) * N + n] : 0.f;
    __half h = __float2half_rn(v);
    bh[i] = h;
    bl[i] = __float2half_rn(v - __half2float(h));
}

// ---------------- fused mid kernel: ballquery CTAs + G-GEMM CTAs ----------------
// bid < 2048: ball query (warp per centroid). bid >= 2048: G = points.W0[3:67]+b0, mb = bid-2048.
__global__ __launch_bounds__(256, 2) void mid_kernel(
    const float* __restrict__ xyz, const float* __restrict__ new_xyz,
    int* __restrict__ gidx,
    const float* __restrict__ points,
    const __half* __restrict__ BH, const __half* __restrict__ BL,
    const float* __restrict__ bias,
    float* __restrict__ G)
{
    extern __shared__ __align__(16) char dyn[];
    const int tid = threadIdx.x;

    if (blockIdx.x < 2048) {
        // ---------- ball query ----------
        const int w    = blockIdx.x * 8 + (tid >> 5);
        const int lane = tid & 31;
        const int b    = w >> 10;
        const float* X = xyz + (size_t)b * NPTS * 3;

        const float cx = new_xyz[(size_t)w*3+0];
        const float cy = new_xyz[(size_t)w*3+1];
        const float cz = new_xyz[(size_t)w*3+2];
        const float ss = cx*cx + cy*cy + cz*cz;

        int cnt = 0, firstIdx = 0;
        int* out = gidx + (size_t)w * NSAMP;

        for (int base = 0; base < NPTS && cnt < NSAMP; base += 32) {
            const int j = base + lane;
            const float x = X[3*j], y = X[3*j+1], z = X[3*j+2];
            const float pp  = x*x + y*y + z*z;
            const float dot = x*cx + y*cy + z*cz;
            const float d   = (-2.0f*dot + ss) + pp;
            const bool  in  = !(d > RAD2);
            unsigned mask = __ballot_sync(0xffffffffu, in);
            if (cnt == 0 && mask) firstIdx = base + (__ffs(mask) - 1);
            int rank = __popc(mask & ((1u << lane) - 1u));
            int slot = cnt + rank;
            if (in && slot < NSAMP) out[slot] = j;
            cnt += __popc(mask);
        }
        for (int t = cnt + lane; t < NSAMP; t += 32) out[t] = firstIdx;
        return;
    }

    // ---------- G-GEMM: BN=64, K=64, A f32, B split hi/lo, f32 output ----------
    constexpr int BN = 64, K = 64;
    constexpr int LDA = K + 8, LDB = BN + 8;
    __half* aS  = (__half*)dyn;
    __half* bHi = aS + 128 * LDA;
    __half* bLo = bHi + K * LDB;

    const int mb = blockIdx.x - 2048;
    const int m0 = mb * 128;

    const int wid = tid >> 5, lane = tid & 31;
    const int wm = wid >> 1, wn = wid & 1;
    const int mW = wm * 32, nW = wn * 32;
    constexpr int NT = 4;       // BN/16

    float acc[2][NT][4];
#pragma unroll
    for (int i = 0; i < 2; i++)
#pragma unroll
        for (int j = 0; j < NT; j++)
#pragma unroll
            for (int q = 0; q < 4; q++) acc[i][j][q] = 0.f;

    // stage A (f32 -> fp16 single)
    for (int idx = tid; idx < 128 * (K/2); idx += 256) {
        const int r = idx / (K/2);
        const int kl = 2 * (idx - r * (K/2));
        const float2 f = *(const float2*)(points + (size_t)(m0 + r) * K + kl);
        *(uint32_t*)(aS + r * LDA + kl) = packh2(f.x, f.y);
    }
    // stage B hi/lo
    for (int idx = tid; idx < K * (BN/2); idx += 256) {
        const int k = idx / (BN/2);
        const int n = 2 * (idx - k * (BN/2));
        *(uint32_t*)(bHi + k * LDB + n) = *(const uint32_t*)(BH + (size_t)k * BN + n);
        *(uint32_t*)(bLo + k * LDB + n) = *(const uint32_t*)(BL + (size_t)k * BN + n);
    }
    __syncthreads();

    const uint32_t aU   = smem_u32(aS)  + (uint32_t)(mW + (lane & 15)) * (LDA * 2) + (lane >> 4) * 16;
    const uint32_t bHiU = smem_u32(bHi) + (uint32_t)(lane & 15) * (LDB * 2) + (uint32_t)nW * 2 + (lane >> 4) * 16;
    const uint32_t bLoU = smem_u32(bLo) + (uint32_t)(lane & 15) * (LDB * 2) + (uint32_t)nW * 2 + (lane >> 4) * 16;

#pragma unroll
    for (int ks = 0; ks < K/16; ks++) {
        uint32_t a0[4], a1[4];
        ldsm4(a0, aU + ks * 32);
        ldsm4(a1, aU + 16 * LDA * 2 + ks * 32);
#pragma unroll
        for (int ng = 0; ng < NT / 2; ng++) {
            uint32_t bh[4], bl[4];
            const uint32_t bo = (uint32_t)ks * (16 * LDB * 2) + ng * 32;
            ldsm4t(bh, bHiU + bo);
            ldsm4t(bl, bLoU + bo);
            mma_f16(acc[0][ng*2+0], a0, bh[0], bh[1]);
            mma_f16(acc[0][ng*2+1], a0, bh[2], bh[3]);
            mma_f16(acc[1][ng*2+0], a1, bh[0], bh[1]);
            mma_f16(acc[1][ng*2+1], a1, bh[2], bh[3]);
            mma_f16(acc[0][ng*2+0], a0, bl[0], bl[1]);
            mma_f16(acc[0][ng*2+1], a0, bl[2], bl[3]);
            mma_f16(acc[1][ng*2+0], a1, bl[0], bl[1]);
            mma_f16(acc[1][ng*2+1], a1, bl[2], bl[3]);
        }
    }

    const int r0 = lane >> 2;
#pragma unroll
    for (int nt = 0; nt < NT; nt++) {
        const int colLocal = nW + nt * 8 + (lane & 3) * 2;
        const float b0v = __ldg(bias + colLocal);
        const float b1v = __ldg(bias + colLocal + 1);
        const size_t base = (size_t)(m0 + mW + r0) * BN + colLocal;
        *(float2*)(G + base)          = make_float2(acc[0][nt][0] + b0v, acc[0][nt][1] + b1v);
        *(float2*)(G + base +  8*BN)  = make_float2(acc[0][nt][2] + b0v, acc[0][nt][3] + b1v);
        *(float2*)(G + base + 16*BN)  = make_float2(acc[1][nt][0] + b0v, acc[1][nt][1] + b1v);
        *(float2*)(G + base + 24*BN)  = make_float2(acc[1][nt][2] + b0v, acc[1][nt][3] + b1v);
    }
}

// ---------------- HMMA GEMM layer2: 256 threads, single fp16 B, K=64 ----------------
template<int BN, int NTOT, int KORIG, int MINB>
__global__ void __launch_bounds__(256, MINB) gemm_l2(
    const uint32_t* __restrict__ A,
    const __half* __restrict__ BH,
    const float* __restrict__ bias,
    const float* __restrict__ scale, const float* __restrict__ shift,
    uint32_t* __restrict__ Y,
    float* __restrict__ partSum, float* __restrict__ partSq)
{
    extern __shared__ __align__(16) char dyn[];
    constexpr int KC = 64;
    constexpr int LDA = KC + 8;
    constexpr int LDB = BN + 8;
    __half* aS  = (__half*)dyn;
    __half* bHi = aS + 128 * LDA;

    const int tid = threadIdx.x;
    const int mb = blockIdx.y;
    const int m0 = mb * 128, n0 = 0;

    const int wid = tid >> 5, lane = tid & 31;
    const int wm = wid >> 1, wn = wid & 1;
    const int mW = wm * 32, nW = wn * (BN / 2);
    constexpr int NT = BN / 16;

    float acc[2][NT][4];
#pragma unroll
    for (int i = 0; i < 2; i++)
#pragma unroll
        for (int j = 0; j < NT; j++)
#pragma unroll
            for (int q = 0; q < 4; q++) acc[i][j][q] = 0.f;

    for (int idx = tid; idx < 128 * (KC/2); idx += 256) {
        const int r = idx / (KC/2);
        const int kl = 2 * (idx - r * (KC/2));
        const uint32_t w = A[((size_t)(m0 + r) * KORIG + kl) >> 1];
        const float2 f = __half22float2(*(const __half2*)&w);
        float v0 = fmaxf(fmaf(f.x, __ldg(scale + kl),     __ldg(shift + kl)),     0.f);
        float v1 = fmaxf(fmaf(f.y, __ldg(scale + kl + 1), __ldg(shift + kl + 1)), 0.f);
        *(uint32_t*)(aS + r * LDA + kl) = packh2(v0, v1);
    }
    for (int idx = tid; idx < KC * (BN/2); idx += 256) {
        const int k = idx / (BN/2);
        const int n = 2 * (idx - k * (BN/2));
        *(uint32_t*)(bHi + k * LDB + n) = *(const uint32_t*)(BH + (size_t)k * NTOT + n);
    }
    __syncthreads();

    const uint32_t aU   = smem_u32(aS)  + (uint32_t)(mW + (lane & 15)) * (LDA * 2) + (lane >> 4) * 16;
    const uint32_t bHiU = smem_u32(bHi) + (uint32_t)(lane & 15) * (LDB * 2) + (uint32_t)nW * 2 + (lane >> 4) * 16;

#pragma unroll
    for (int ks = 0; ks < KC/16; ks++) {
        uint32_t a0[4], a1[4];
        ldsm4(a0, aU + ks * 32);
        ldsm4(a1, aU + 16 * LDA * 2 + ks * 32);
#pragma unroll
        for (int ng = 0; ng < NT / 2; ng++) {
            uint32_t bh[4];
            const uint32_t bo = (uint32_t)ks * (16 * LDB * 2) + ng * 32;
            ldsm4t(bh, bHiU + bo);
            mma_f16(acc[0][ng*2+0], a0, bh[0], bh[1]);
            mma_f16(acc[0][ng*2+1], a0, bh[2], bh[3]);
            mma_f16(acc[1][ng*2+0], a1, bh[0], bh[1]);
            mma_f16(acc[1][ng*2+1], a1, bh[2], bh[3]);
        }
    }
    __syncthreads();

    float* sSum = (float*)dyn;
    float* sSq  = sSum + 4 * BN;

    const int r0 = lane >> 2;
#pragma unroll
    for (int nt = 0; nt < NT; nt++) {
        const int colLocal = nW + nt * 8 + (lane & 3) * 2;
        const float b0 = __ldg(bias + n0 + colLocal);
        const float b1 = __ldg(bias + n0 + colLocal + 1);
        float v0 = acc[0][nt][0] + b0, v1 = acc[0][nt][1] + b1;
        float v2 = acc[0][nt][2] + b0, v3 = acc[0][nt][3] + b1;
        float v4 = acc[1][nt][0] + b0, v5 = acc[1][nt][1] + b1;
        float v6 = acc[1][nt][2] + b0, v7 = acc[1][nt][3] + b1;
        {
            const size_t base = ((size_t)(m0 + mW + r0) * NTOT + colLocal) >> 1;
            const size_t rstep = (size_t)8 * NTOT >> 1;
            Y[base]             = packh2(v0, v1);
            Y[base +     rstep] = packh2(v2, v3);
            Y[base + 2 * rstep] = packh2(v4, v5);
            Y[base + 3 * rstep] = packh2(v6, v7);
        }
        float s0 = v0+v2+v4+v6,              s1 = v1+v3+v5+v7;
        float q0 = v0*v0+v2*v2+v4*v4+v6*v6,  q1 = v1*v1+v3*v3+v5*v5+v7*v7;
#pragma unroll
        for (int d = 4; d < 32; d <<= 1) {
            s0 += __shfl_xor_sync(0xffffffffu, s0, d);
            s1 += __shfl_xor_sync(0xffffffffu, s1, d);
            q0 += __shfl_xor_sync(0xffffffffu, q0, d);
            q1 += __shfl_xor_sync(0xffffffffu, q1, d);
        }
        if (lane < 4) {
            sSum[wm*BN + colLocal] = s0;  sSum[wm*BN + colLocal + 1] = s1;
            sSq [wm*BN + colLocal] = q0;  sSq [wm*BN + colLocal + 1] = q1;
        }
    }
    __syncthreads();
    for (int n = tid; n < BN; n += 256) {
        float s = sSum[n] + sSum[BN + n] + sSum[2*BN + n] + sSum[3*BN + n];
        float q = sSq [n] + sSq [BN + n] + sSq [2*BN + n] + sSq [3*BN + n];
        partSum[(size_t)n * MBLK + mb] = s;
        partSq [(size_t)n * MBLK + mb] = q;
    }
}

// ---------------- Layer-3 wide GEMM: 512 threads, BN=256, double-buffered K chunks ----------------
__global__ void __launch_bounds__(512, 1) gemm_mma_w3(
    const uint32_t* __restrict__ A,
    const __half* __restrict__ BH,
    const float* __restrict__ bias,
    const float* __restrict__ scale, const float* __restrict__ shift,
    float* __restrict__ partSum, float* __restrict__ partSq,
    float* __restrict__ gmax, float* __restrict__ gmin)
{
    extern __shared__ __align__(16) char dyn[];
    constexpr int BN  = 256, KC = 64, KORIG = 128;
    constexpr int LDA = KC + 8;
    constexpr int LDB = BN + 8;
    constexpr int ABUF = 128 * LDA;     // halfs
    constexpr int BBUF = KC * LDB;      // halfs
    __half* aS0 = (__half*)dyn;
    __half* aS1 = aS0 + ABUF;
    __half* bH0 = aS1 + ABUF;
    __half* bH1 = bH0 + BBUF;

    const int tid = threadIdx.x;
    const int mb = blockIdx.x;
    const int m0 = mb * 128;

    const int wid = tid >> 5, lane = tid & 31;
    const int wm = wid >> 2, wn = wid & 3;
    const int mW = wm * 32, nW = wn * 64;
    constexpr int NT = 8;

    float acc[2][NT][4];
#pragma unroll
    for (int i = 0; i < 2; i++)
#pragma unroll
        for (int j = 0; j < NT; j++)
#pragma unroll
            for (int q = 0; q < 4; q++) acc[i][j][q] = 0.f;

    const uint32_t aOff = (uint32_t)(mW + (lane & 15)) * (LDA * 2) + (lane >> 4) * 16;
    const uint32_t bOff = (uint32_t)(lane & 15) * (LDB * 2) + (uint32_t)nW * 2 + (lane >> 4) * 16;
    const uint32_t aU0 = smem_u32(aS0) + aOff, aU1 = smem_u32(aS1) + aOff;
    const uint32_t bU0 = smem_u32(bH0) + bOff, bU1 = smem_u32(bH1) + bOff;

    auto compute = [&](uint32_t aU, uint32_t bU) {
#pragma unroll
        for (int ks = 0; ks < KC/16; ks++) {
            uint32_t a0[4], a1[4];
            ldsm4(a0, aU + ks * 32);
            ldsm4(a1, aU + 16 * LDA * 2 + ks * 32);
#pragma unroll
            for (int ng = 0; ng < NT / 2; ng++) {
                uint32_t bh[4];
                const uint32_t bo = (uint32_t)ks * (16 * LDB * 2) + ng * 32;
                ldsm4t(bh, bU + bo);
                mma_f16(acc[0][ng*2+0], a0, bh[0], bh[1]);
                mma_f16(acc[0][ng*2+1], a0, bh[2], bh[3]);
                mma_f16(acc[1][ng*2+0], a1, bh[0], bh[1]);
                mma_f16(acc[1][ng*2+1], a1, bh[2], bh[3]);
            }
        }
    };

    // ---- stage chunk 0 directly ----
    for (int idx = tid; idx < 128 * (KC/2); idx += 512) {
        const int r = idx / (KC/2);
        const int kl = 2 * (idx - r * (KC/2));
        const uint32_t w = A[((size_t)(m0 + r) * KORIG + kl) >> 1];
        const float2 f = __half22float2(*(const __half2*)&w);
        float v0 = fmaxf(fmaf(f.x, __ldg(scale + kl),     __ldg(shift + kl)),     0.f);
        float v1 = fmaxf(fmaf(f.y, __ldg(scale + kl + 1), __ldg(shift + kl + 1)), 0.f);
        *(uint32_t*)(aS0 + r * LDA + kl) = packh2(v0, v1);
    }
    for (int idx = tid; idx < KC * (BN/2); idx += 512) {
        const int k = idx / (BN/2);
        const int n = 2 * (idx - k * (BN/2));
        *(uint32_t*)(bH0 + k * LDB + n) = *(const uint32_t*)(BH + (size_t)k * BN + n);
    }
    __syncthreads();

    // ---- prefetch chunk 1 into registers (LDGs in flight during compute) ----
    uint32_t pa[8];
#pragma unroll
    for (int it = 0; it < 8; it++) {
        const int idx = tid + it * 512;
        const int r = idx / (KC/2);
        const int kl = 2 * (idx - r * (KC/2));
        pa[it] = A[((size_t)(m0 + r) * KORIG + 64 + kl) >> 1];
    }
    uint32_t pb[16];
#pragma unroll
    for (int it = 0; it < 16; it++) {
        const int idx = tid + it * 512;
        const int k = idx / (BN/2);
        const int n = 2 * (idx - k * (BN/2));
        pb[it] = *(const uint32_t*)(BH + (size_t)(64 + k) * BN + n);
    }

    compute(aU0, bU0);

    // ---- convert + store chunk 1 ----
#pragma unroll
    for (int it = 0; it < 8; it++) {
        const int idx = tid + it * 512;
        const int r = idx / (KC/2);
        const int kl = 2 * (idx - r * (KC/2));
        const int kk = 64 + kl;
        const float2 f = __half22float2(*(const __half2*)&pa[it]);
        float v0 = fmaxf(fmaf(f.x, __ldg(scale + kk),     __ldg(shift + kk)),     0.f);
        float v1 = fmaxf(fmaf(f.y, __ldg(scale + kk + 1), __ldg(shift + kk + 1)), 0.f);
        *(uint32_t*)(aS1 + r * LDA + kl) = packh2(v0, v1);
    }
#pragma unroll
    for (int it = 0; it < 16; it++) {
        const int idx = tid + it * 512;
        const int k = idx / (BN/2);
        const int n = 2 * (idx - k * (BN/2));
        *(uint32_t*)(bH1 + k * LDB + n) = pb[it];
    }
    __syncthreads();

    compute(aU1, bU1);
    __syncthreads();

    // ---- epilogue ----
    float* sSum = (float*)dyn;
    float* sSq  = sSum + 4 * BN;

#pragma unroll
    for (int nt = 0; nt < NT; nt++) {
        const int colLocal = nW + nt * 8 + (lane & 3) * 2;
        const float b0 = __ldg(bias + colLocal);
        const float b1 = __ldg(bias + colLocal + 1);
        float v0 = acc[0][nt][0] + b0, v1 = acc[0][nt][1] + b1;
        float v2 = acc[0][nt][2] + b0, v3 = acc[0][nt][3] + b1;
        float v4 = acc[1][nt][0] + b0, v5 = acc[1][nt][1] + b1;
        float v6 = acc[1][nt][2] + b0, v7 = acc[1][nt][3] + b1;
        float s0 = v0+v2+v4+v6,              s1 = v1+v3+v5+v7;
        float q0 = v0*v0+v2*v2+v4*v4+v6*v6,  q1 = v1*v1+v3*v3+v5*v5+v7*v7;
        float mx0 = fmaxf(fmaxf(v0,v2), fmaxf(v4,v6)), mx1 = fmaxf(fmaxf(v1,v3), fmaxf(v5,v7));
        float mn0 = fminf(fminf(v0,v2), fminf(v4,v6)), mn1 = fminf(fminf(v1,v3), fminf(v5,v7));
#pragma unroll
        for (int d = 4; d < 32; d <<= 1) {
            s0 += __shfl_xor_sync(0xffffffffu, s0, d);
            s1 += __shfl_xor_sync(0xffffffffu, s1, d);
            q0 += __shfl_xor_sync(0xffffffffu, q0, d);
            q1 += __shfl_xor_sync(0xffffffffu, q1, d);
            mx0 = fmaxf(mx0, __shfl_xor_sync(0xffffffffu, mx0, d));
            mx1 = fmaxf(mx1, __shfl_xor_sync(0xffffffffu, mx1, d));
            mn0 = fminf(mn0, __shfl_xor_sync(0xffffffffu, mn0, d));
            mn1 = fminf(mn1, __shfl_xor_sync(0xffffffffu, mn1, d));
        }
        if (lane < 4) {
            sSum[wm*BN + colLocal] = s0;  sSum[wm*BN + colLocal + 1] = s1;
            sSq [wm*BN + colLocal] = q0;  sSq [wm*BN + colLocal + 1] = q1;
            const size_t grp = (size_t)(mb * 4 + wm) * CH3 + colLocal;
            gmax[grp]     = mx0;  gmax[grp + 1] = mx1;
            gmin[grp]     = mn0;  gmin[grp + 1] = mn1;
        }
    }
    __syncthreads();
    for (int n = tid; n < BN; n += 512) {
        float s = sSum[n] + sSum[BN + n] + sSum[2*BN + n] + sSum[3*BN + n];
        float q = sSq [n] + sSq [BN + n] + sSq [2*BN + n] + sSq [3*BN + n];
        partSum[(size_t)n * MBLK + mb] = s;
        partSq [(size_t)n * MBLK + mb] = q;
    }
}

// ---------------- y1build ----------------
__global__ __launch_bounds__(256) void y1build_kernel(
    const float* __restrict__ G, const int* __restrict__ gidx,
    const float* __restrict__ xyz, const float* __restrict__ nxyz,
    const float* __restrict__ w0,
    uint32_t* __restrict__ y1,
    float* __restrict__ partSum, float* __restrict__ partSq)
{
    __shared__ int   sIdx[128];
    __shared__ float sCen[12];
    __shared__ float sW[192];
    __shared__ float sXn[128*3];
    __shared__ float sRed[1024];
    const int mb = blockIdx.x, m0 = mb * 128, tid = threadIdx.x;
    const int b = mb >> 8;

    if (tid < 128) sIdx[tid] = gidx[m0 + tid];
    if (tid < 12)  sCen[tid] = nxyz[(size_t)(mb * 4) * 3 + tid];
    if (tid < 192) sW[tid]   = w0[tid];
    __syncthreads();
    if (tid < 128) {
        const int g = tid >> 5;
        const int j = sIdx[tid];
        const float* xp = xyz + ((size_t)b * NPTS + j) * 3;
        sXn[tid*3+0] = xp[0] - sCen[g*3+0];
        sXn[tid*3+1] = xp[1] - sCen[g*3+1];
        sXn[tid*3+2] = xp[2] - sCen[g*3+2];
    }
    __syncthreads();

    const int cp = tid & 31;
    const int rg = tid >> 5;
    const int c0 = 2 * cp;
    const float wx0 = sW[c0],   wy0 = sW[64+c0],   wz0 = sW[128+c0];
    const float wx1 = sW[c0+1], wy1 = sW[64+c0+1], wz1 = sW[128+c0+1];

    float s0 = 0.f, s1 = 0.f, q0 = 0.f, q1 = 0.f;
#pragma unroll 4
    for (int rr = 0; rr < 16; rr++) {
        const int r = rg * 16 + rr;
        const int j = sIdx[r];
        const float xn = sXn[r*3], yn = sXn[r*3+1], zn = sXn[r*3+2];
        const float2 gv = *(const float2*)(G + ((size_t)b * NPTS + j) * CH1 + c0);
        float v0 = fmaf(zn, wz0, fmaf(yn, wy0, fmaf(xn, wx0, gv.x)));
        float v1 = fmaf(zn, wz1, fmaf(yn, wy1, fmaf(xn, wx1, gv.y)));
        y1[(size_t)(m0 + r) * (CH1/2) + cp] = packh2(v0, v1);
        s0 += v0; s1 += v1; q0 += v0*v0; q1 += v1*v1;
    }
    sRed[rg*64 + c0]       = s0;  sRed[rg*64 + c0 + 1]       = s1;
    sRed[512 + rg*64 + c0] = q0;  sRed[512 + rg*64 + c0 + 1] = q1;
    __syncthreads();
    if (rg == 0) {
        float S0 = 0.f, S1 = 0.f, Q0 = 0.f, Q1 = 0.f;
#pragma unroll
        for (int g2 = 0; g2 < 8; g2++) {
            S0 += sRed[g2*64 + c0];       S1 += sRed[g2*64 + c0 + 1];
            Q0 += sRed[512 + g2*64 + c0]; Q1 += sRed[512 + g2*64 + c0 + 1];
        }
        partSum[(size_t)c0 * MBLK + mb]       = S0;
        partSum[(size_t)(c0 + 1) * MBLK + mb] = S1;
        partSq [(size_t)c0 * MBLK + mb]       = Q0;
        partSq [(size_t)(c0 + 1) * MBLK + mb] = Q1;
    }
}

// ---------------- fold partials -> scale/shift ----------------
__global__ __launch_bounds__(256) void stats_kernel(const float* __restrict__ partSum,
                                                    const float* __restrict__ partSq,
                                                    int N,
                                                    const float* __restrict__ g,
                                                    const float* __restrict__ bt,
                                                    float* __restrict__ scale,
                                                    float* __restrict__ shift)
{
    const int c = blockIdx.x, tid = threadIdx.x;
    __shared__ float ss[256], sq[256];
    float a = 0.f, b2 = 0.f;
    const float* ps = partSum + (size_t)c * MBLK;
    const float* pq = partSq  + (size_t)c * MBLK;
    for (int mb = tid; mb < MBLK; mb += 256) {
        a  += ps[mb];
        b2 += pq[mb];
    }
    ss[tid] = a; sq[tid] = b2;
    __syncthreads();
    for (int s = 128; s > 0; s >>= 1) {
        if (tid < s) { ss[tid] += ss[tid+s]; sq[tid] += sq[tid+s]; }
        __syncthreads();
    }
    if (tid == 0) {
        const float invM = 1.0f / (float)MTOT;
        float mean = ss[0] * invM;
        float var  = sq[0] * invM - mean * mean;
        float sc   = g[c] / sqrtf(var + BNEPS);
        scale[c] = sc;
        shift[c] = bt[c] - mean * sc;
    }
}

// ---------------- final pool ----------------
__global__ __launch_bounds__(256) void finalpool_kernel(const float* __restrict__ gmax,
                                                        const float* __restrict__ gmin,
                                                        const float* __restrict__ scale,
                                                        const float* __restrict__ shift,
                                                        float* __restrict__ out)
{
    const int g = blockIdx.x, c = threadIdx.x;
    const float sc = scale[c], sh = shift[c];
    const float v = (sc >= 0.f) ? gmax[(size_t)g * CH3 + c] : gmin[(size_t)g * CH3 + c];
    out[(size_t)g * CH3 + c] = fmaxf(fmaf(v, sc, sh), 0.f);
}

// ---------------- launch ----------------
extern "C" void kernel_launch(void* const* d_in, const int* in_sizes, int n_in,
                              void* d_out, int out_size)
{
    const float* xyz    = (const float*)d_in[0];
    const float* points = (const float*)d_in[1];
    const float* w0  = (const float*)d_in[2];
    const float* b0  = (const float*)d_in[3];
    const float* g0  = (const float*)d_in[4];
    const float* bt0 = (const float*)d_in[5];
    const float* w1  = (const float*)d_in[6];
    const float* b1  = (const float*)d_in[7];
    const float* g1  = (const float*)d_in[8];
    const float* bt1 = (const float*)d_in[9];
    const float* w2  = (const float*)d_in[10];
    const float* b2  = (const float*)d_in[11];
    const float* g2  = (const float*)d_in[12];
    const float* bt2 = (const float*)d_in[13];

    float* out        = (float*)d_out;
    float* new_xyz    = out;
    float* new_points = out + (size_t)BATCH*SPTS*3;

    float *Gp, *part, *scale, *shift, *gmax, *gmin;
    uint32_t *y1, *y2;
    int* gidx;
    __half *bh0, *bl0, *bh1, *bl1, *bh2, *bl2;
    cudaGetSymbolAddress((void**)&Gp,    g_G);
    cudaGetSymbolAddress((void**)&y1,    g_y1);
    cudaGetSymbolAddress((void**)&y2,    g_y2);
    cudaGetSymbolAddress((void**)&part,  g_part);
    cudaGetSymbolAddress((void**)&scale, g_scale);
    cudaGetSymbolAddress((void**)&shift, g_shift);
    cudaGetSymbolAddress((void**)&gidx,  g_gidx);
    cudaGetSymbolAddress((void**)&gmax,  g_gmax);
    cudaGetSymbolAddress((void**)&gmin,  g_gmin);
    cudaGetSymbolAddress((void**)&bh0,   g_bh0);
    cudaGetSymbolAddress((void**)&bl0,   g_bl0);
    cudaGetSymbolAddress((void**)&bh1,   g_bh1);
    cudaGetSymbolAddress((void**)&bl1,   g_bl1);
    cudaGetSymbolAddress((void**)&bh2,   g_bh2);
    cudaGetSymbolAddress((void**)&bl2,   g_bl2);

    float* partSum = part;
    float* partSq  = part + (size_t)MBLK * CH3;

    constexpr int SMMID = (128*(64+8) + 2*64*(64+8))  * 2;  //  36,864 (mid G part)
    constexpr int SM2   = (128*(64+8) + 64*(128+8))   * 2;  //  35,840
    constexpr int SMW   = (2*128*(64+8) + 2*64*(256+8)) * 2; // 104,448 (double-buffered)

    static bool attrDone = false;
    if (!attrDone) {
        cudaFuncSetAttribute(mid_kernel,
                             cudaFuncAttributeMaxDynamicSharedMemorySize, SMMID);
        cudaFuncSetAttribute(gemm_l2<128, 128, 64, 2>,
                             cudaFuncAttributeMaxDynamicSharedMemorySize, SM2);
        cudaFuncSetAttribute(gemm_mma_w3,
                             cudaFuncAttributeMaxDynamicSharedMemorySize, SMW);
        attrDone = true;
    }

    prep_kernel<<<(64*64 + 255)/256, 256>>>(w0, 64, CH1, 64, 3, bh0, bl0);
    prep_kernel<<<(64*128 + 255)/256, 256>>>(w1, CH1, CH2, 64, 0, bh1, bl1);
    prep_kernel<<<(128*256 + 255)/256, 256>>>(w2, CH2, CH3, 128, 0, bh2, bl2);

    fps_kernel<<<BATCH, 512>>>(xyz, new_xyz);

    // fused: ballquery (2048 CTAs) + G-GEMM (512 CTAs) run concurrently
    mid_kernel<<<2048 + 512, 256, SMMID>>>(xyz, new_xyz, gidx,
                                           points, bh0, bl0, b0, Gp);

    y1build_kernel<<<MBLK, 256>>>(Gp, gidx, xyz, new_xyz, w0, y1, partSum, partSq);
    stats_kernel<<<CH1, 256>>>(partSum, partSq, CH1, g0, bt0, scale, shift);

    gemm_l2<128, 128, 64, 2><<<dim3(1, MBLK), 256, SM2>>>(
        y1, bh1, b1, scale, shift, y2, partSum, partSq);
    stats_kernel<<<CH2, 256>>>(partSum, partSq, CH2, g1, bt1, scale, shift);

    gemm_mma_w3<<<MBLK, 512, SMW>>>(
        y2, bh2, b2, scale, shift, partSum, partSq, gmax, gmin);
    stats_kernel<<<CH3, 256>>>(partSum, partSq, CH3, g2, bt2, scale, shift);

    finalpool_kernel<<<BATCH*SPTS, 256>>>(gmax, gmin, scale, shift, new_points);
}

// round 15
// speedup vs baseline: 1.2010x; 1.2010x over previous
#include <cuda_runtime.h>
#include <cuda_fp16.h>
#include <math.h>
#include <stdint.h>

// ---------------- problem constants ----------------
#define BATCH 16
#define NPTS  4096
#define DFEAT 64
#define SPTS  1024
#define NSAMP 32
#define CH0   67
#define CH1   64
#define CH2   128
#define CH3   256
#define MTOT  (BATCH*SPTS*NSAMP)   // 524288
#define MBLK  (MTOT/128)           // 4096
#define RAD2  0.04f
#define BNEPS 1e-5f

typedef unsigned long long ull;

// ---------------- device scratch ----------------
__device__ float    g_G[(size_t)BATCH*NPTS*CH1];
__device__ uint32_t g_y1[(size_t)MTOT*CH1/2];      // fp16 pairs
__device__ uint32_t g_y2[(size_t)MTOT*CH2/2];      // fp16 pairs
__device__ int   g_gidx[BATCH*SPTS*NSAMP];
__device__ float g_part[2*(size_t)MBLK*CH3];       // transposed [n][MBLK]
__device__ float g_scale[CH3];
__device__ float g_shift[CH3];
__device__ float g_gmax[(size_t)BATCH*SPTS*CH3];
__device__ float g_gmin[(size_t)BATCH*SPTS*CH3];
__device__ __half g_bh0[64*64],   g_bl0[64*64];
__device__ __half g_bh1[64*128],  g_bl1[64*128];
__device__ __half g_bh2[128*256], g_bl2[128*256];

// ---------------- helpers ----------------
__device__ __forceinline__ uint32_t smem_u32(const void* p) {
    uint32_t a;
    asm("{ .reg .u64 t; cvta.to.shared.u64 t, %1; cvt.u32.u64 %0, t; }" : "=r"(a) : "l"(p));
    return a;
}
__device__ __forceinline__ void ldsm4(uint32_t* r, uint32_t a) {
    asm volatile("ldmatrix.sync.aligned.m8n8.x4.shared.b16 {%0,%1,%2,%3}, [%4];"
                 : "=r"(r[0]), "=r"(r[1]), "=r"(r[2]), "=r"(r[3]) : "r"(a));
}
__device__ __forceinline__ void ldsm4t(uint32_t* r, uint32_t a) {
    asm volatile("ldmatrix.sync.aligned.m8n8.x4.trans.shared.b16 {%0,%1,%2,%3}, [%4];"
                 : "=r"(r[0]), "=r"(r[1]), "=r"(r[2]), "=r"(r[3]) : "r"(a));
}
__device__ __forceinline__ void mma_f16(float* c, const uint32_t* a, uint32_t b0, uint32_t b1) {
    asm volatile(
        "mma.sync.aligned.m16n8k16.row.col.f32.f16.f16.f32 "
        "{%0,%1,%2,%3}, {%4,%5,%6,%7}, {%8,%9}, {%0,%1,%2,%3};"
        : "+f"(c[0]), "+f"(c[1]), "+f"(c[2]), "+f"(c[3])
        : "r"(a[0]), "r"(a[1]), "r"(a[2]), "r"(a[3]), "r"(b0), "r"(b1));
}
__device__ __forceinline__ uint32_t packh2(float v0, float v1) {
    __half2 h = __floats2half2_rn(v0, v1);
    return *(uint32_t*)&h;
}

// ---------------- FPS (512 threads, packed f32x2, REDUX tails) ----------------
__global__ __launch_bounds__(512) void fps_kernel(const float* __restrict__ xyz,
                                                  float* __restrict__ new_xyz)
{
    __shared__ float sx[NPTS], sy[NPTS], sz[NPTS];
    __shared__ unsigned s_val[2][16], s_low[2][16];
    const int b = blockIdx.x, tid = threadIdx.x;
    const int lane = tid & 31, wid = tid >> 5;
    const float* X = xyz + (size_t)b * NPTS * 3;

    ull pxp[4], pyp[4], pzp[4];
    float dist[8];
#pragma unroll
    for (int t = 0; t < 8; t++) dist[t] = 1e10f;
#pragma unroll
    for (int t = 0; t < 4; t++) {
        const int j0 = tid + (2*t) * 512, j1 = tid + (2*t+1) * 512;
        float x0 = X[3*j0], y0 = X[3*j0+1], z0 = X[3*j0+2];
        float x1 = X[3*j1], y1 = X[3*j1+1], z1 = X[3*j1+2];
        sx[j0] = x0; sy[j0] = y0; sz[j0] = z0;
        sx[j1] = x1; sy[j1] = y1; sz[j1] = z1;
        asm("mov.b64 %0, {%1,%2};" : "=l"(pxp[t]) : "f"(x0), "f"(x1));
        asm("mov.b64 %0, {%1,%2};" : "=l"(pyp[t]) : "f"(y0), "f"(y1));
        asm("mov.b64 %0, {%1,%2};" : "=l"(pzp[t]) : "f"(z0), "f"(z1));
    }
    __syncthreads();

    int far = 0;
    for (int i = 0; i < SPTS; i++) {
        const float cx = sx[far], cy = sy[far], cz = sz[far];
        if (tid == 0) {
            float* o = new_xyz + ((size_t)b * SPTS + i) * 3;
            o[0] = cx; o[1] = cy; o[2] = cz;
        }
        if (i == SPTS - 1) break;

        const float mx = -cx, my = -cy, mz = -cz;
        ull ncx, ncy, ncz;
        asm("mov.b64 %0, {%1,%1};" : "=l"(ncx) : "f"(mx));
        asm("mov.b64 %0, {%1,%1};" : "=l"(ncy) : "f"(my));
        asm("mov.b64 %0, {%1,%1};" : "=l"(ncz) : "f"(mz));

        float bv = -1.0f; int bi = 0;
#pragma unroll
        for (int t = 0; t < 4; t++) {
            ull dx, dy, dz, dd;
            asm("add.rn.f32x2 %0, %1, %2;" : "=l"(dx) : "l"(pxp[t]), "l"(ncx));
            asm("add.rn.f32x2 %0, %1, %2;" : "=l"(dy) : "l"(pyp[t]), "l"(ncy));
            asm("add.rn.f32x2 %0, %1, %2;" : "=l"(dz) : "l"(pzp[t]), "l"(ncz));
            asm("mul.rn.f32x2 %0, %1, %2;" : "=l"(dd) : "l"(dx), "l"(dx));
            asm("fma.rn.f32x2 %0, %1, %2, %3;" : "=l"(dd) : "l"(dy), "l"(dy), "l"(dd));
            asm("fma.rn.f32x2 %0, %1, %2, %3;" : "=l"(dd) : "l"(dz), "l"(dz), "l"(dd));
            float d0, d1;
            asm("mov.b64 {%0,%1}, %2;" : "=f"(d0), "=f"(d1) : "l"(dd));
            const float nd0 = fminf(dist[2*t],   d0);
            const float nd1 = fminf(dist[2*t+1], d1);
            dist[2*t]   = nd0;
            dist[2*t+1] = nd1;
            if (nd0 > bv) { bv = nd0; bi = tid + (2*t)   * 512; }
            if (nd1 > bv) { bv = nd1; bi = tid + (2*t+1) * 512; }
        }
        const unsigned vb = __float_as_uint(bv);
        const unsigned m  = __reduce_max_sync(0xffffffffu, vb);
        const unsigned lw = __reduce_max_sync(0xffffffffu,
                                              (vb == m) ? (0xFFFFu - (unsigned)bi) : 0u);
        const int buf = i & 1;
        if (lane == 0) { s_val[buf][wid] = m; s_low[buf][wid] = lw; }
        __syncthreads();

        const unsigned v2 = s_val[buf][lane & 15];
        const unsigned l2 = s_low[buf][lane & 15];
        const unsigned M  = __reduce_max_sync(0xffffffffu, v2);
        const unsigned LW = __reduce_max_sync(0xffffffffu, (v2 == M) ? l2 : 0u);
        far = 0xFFFF - (int)LW;
    }
}

// ---------------- ball query ----------------
__global__ __launch_bounds__(256) void ballquery_kernel(const float* __restrict__ xyz,
                                                        const float* __restrict__ new_xyz,
                                                        int* __restrict__ gidx)
{
    const int w    = blockIdx.x * 8 + (threadIdx.x >> 5);
    const int lane = threadIdx.x & 31;
    const int b    = w >> 10;
    const float* X = xyz + (size_t)b * NPTS * 3;

    const float cx = new_xyz[(size_t)w*3+0];
    const float cy = new_xyz[(size_t)w*3+1];
    const float cz = new_xyz[(size_t)w*3+2];
    const float ss = cx*cx + cy*cy + cz*cz;

    int cnt = 0, firstIdx = 0;
    int* out = gidx + (size_t)w * NSAMP;

    for (int base = 0; base < NPTS && cnt < NSAMP; base += 32) {
        const int j = base + lane;
        const float x = X[3*j], y = X[3*j+1], z = X[3*j+2];
        const float pp  = x*x + y*y + z*z;
        const float dot = x*cx + y*cy + z*cz;
        const float d   = (-2.0f*dot + ss) + pp;
        const bool  in  = !(d > RAD2);
        unsigned mask = __ballot_sync(0xffffffffu, in);
        if (cnt == 0 && mask) firstIdx = base + (__ffs(mask) - 1);
        int rank = __popc(mask & ((1u << lane) - 1u));
        int slot = cnt + rank;
        if (in && slot < NSAMP) out[slot] = j;
        cnt += __popc(mask);
    }
    for (int t = cnt + lane; t < NSAMP; t += 32) out[t] = firstIdx;
}

// ---------------- weight prep ----------------
__global__ __launch_bounds__(256) void prep_kernel(const float* __restrict__ W, int K, int N,
                                                   int KPAD, int KOFF,
                                                   __half* __restrict__ bh,
                                                   __half* __restrict__ bl)
{
    int i = blockIdx.x * 256 + threadIdx.x;
    if (i >= N * KPAD) return;
    int k = i / N, n = i - k * N;
    float v = (k < K) ? W[(size_t)(k + KOFF) * N + n] : 0.f;
    __half h = __float2half_rn(v);
    bh[i] = h;
    bl[i] = __float2half_rn(v - __half2float(h));
}

// ---------------- HMMA GEMM, 256 threads ----------------
// AMODE: 1 = fp16-pair u32 input, 2 = f32 row-major input (via fA).
// BSPLIT: true = B hi+lo (2 MMAs), false = single fp16 B (1 MMA).
template<int BN, int NTOT, int KPAD, int KC, int KORIG, int AMODE, bool BSPLIT,
         bool TRANSFORM, bool STORE_Y, bool YF32, bool PART, int MINB>
__global__ void __launch_bounds__(256, MINB) gemm_mma(
    const uint32_t* __restrict__ A, const float* __restrict__ fA,
    const __half* __restrict__ BH, const __half* __restrict__ BL,
    const float* __restrict__ bias,
    const float* __restrict__ scale, const float* __restrict__ shift,
    uint32_t* __restrict__ Y,
    float* __restrict__ partSum, float* __restrict__ partSq)
{
    extern __shared__ __align__(16) char dyn[];
    constexpr int LDA = KC + 8;
    constexpr int LDB = BN + 8;
    constexpr int NCHUNK = KPAD / KC;
    __half* aS  = (__half*)dyn;
    __half* bHi = aS + 128 * LDA;
    __half* bLo = BSPLIT ? (bHi + KC * LDB) : bHi;

    const int tid = threadIdx.x;
    const int nb = blockIdx.x, mb = blockIdx.y;
    const int m0 = mb * 128, n0 = nb * BN;

    const int wid = tid >> 5, lane = tid & 31;
    const int wm = wid >> 1, wn = wid & 1;
    const int mW = wm * 32, nW = wn * (BN / 2);
    constexpr int NT = BN / 16;
    constexpr int KSTEPS_C = KC / 16;

    float acc[2][NT][4];
#pragma unroll
    for (int i = 0; i < 2; i++)
#pragma unroll
        for (int j = 0; j < NT; j++)
#pragma unroll
            for (int q = 0; q < 4; q++) acc[i][j][q] = 0.f;

    const uint32_t aU   = smem_u32(aS)  + (uint32_t)(mW + (lane & 15)) * (LDA * 2) + (lane >> 4) * 16;
    const uint32_t bHiU = smem_u32(bHi) + (uint32_t)(lane & 15) * (LDB * 2) + (uint32_t)nW * 2 + (lane >> 4) * 16;
    const uint32_t bLoU = smem_u32(bLo) + (uint32_t)(lane & 15) * (LDB * 2) + (uint32_t)nW * 2 + (lane >> 4) * 16;

    for (int ch = 0; ch < NCHUNK; ch++) {
        const int kbase = ch * KC;
        if (ch > 0) __syncthreads();

        constexpr int AIT = 128 * (KC / 2);
        for (int idx = tid; idx < AIT; idx += 256) {
            const int r  = idx / (KC / 2);
            const int p  = idx - r * (KC / 2);
            const int kl = 2 * p;
            const int kk = kbase + kl;
            float v0, v1;
            if (AMODE == 2) {
                const float2 f = *(const float2*)(fA + (size_t)(m0 + r) * KORIG + kk);
                v0 = f.x; v1 = f.y;
            } else {
                const uint32_t w = A[((size_t)(m0 + r) * KORIG + kk) >> 1];
                const float2 f = __half22float2(*(const __half2*)&w);
                v0 = f.x; v1 = f.y;
                if (TRANSFORM) {
                    v0 = fmaxf(fmaf(v0, __ldg(scale + kk),     __ldg(shift + kk)),     0.f);
                    v1 = fmaxf(fmaf(v1, __ldg(scale + kk + 1), __ldg(shift + kk + 1)), 0.f);
                }
            }
            *(uint32_t*)(aS + r * LDA + kl) = packh2(v0, v1);
        }
        constexpr int BIT = KC * (BN / 2);
        for (int idx = tid; idx < BIT; idx += 256) {
            const int k = idx / (BN / 2);
            const int n = 2 * (idx - k * (BN / 2));
            *(uint32_t*)(bHi + k * LDB + n) = *(const uint32_t*)(BH + (size_t)(kbase + k) * NTOT + n0 + n);
            if (BSPLIT)
                *(uint32_t*)(bLo + k * LDB + n) = *(const uint32_t*)(BL + (size_t)(kbase + k) * NTOT + n0 + n);
        }
        __syncthreads();

#pragma unroll
        for (int ks = 0; ks < KSTEPS_C; ks++) {
            uint32_t a0[4], a1[4];
            ldsm4(a0, aU + ks * 32);
            ldsm4(a1, aU + 16 * LDA * 2 + ks * 32);
#pragma unroll
            for (int ng = 0; ng < NT / 2; ng++) {
                uint32_t bh[4];
                const uint32_t bo = (uint32_t)ks * (16 * LDB * 2) + ng * 32;
                ldsm4t(bh, bHiU + bo);
                mma_f16(acc[0][ng*2+0], a0, bh[0], bh[1]);
                mma_f16(acc[0][ng*2+1], a0, bh[2], bh[3]);
                mma_f16(acc[1][ng*2+0], a1, bh[0], bh[1]);
                mma_f16(acc[1][ng*2+1], a1, bh[2], bh[3]);
                if (BSPLIT) {
                    uint32_t bl[4];
                    ldsm4t(bl, bLoU + bo);
                    mma_f16(acc[0][ng*2+0], a0, bl[0], bl[1]);
                    mma_f16(acc[0][ng*2+1], a0, bl[2], bl[3]);
                    mma_f16(acc[1][ng*2+0], a1, bl[0], bl[1]);
                    mma_f16(acc[1][ng*2+1], a1, bl[2], bl[3]);
                }
            }
        }
    }
    __syncthreads();

    float* sSum = (float*)dyn;            // [4][BN]
    float* sSq  = sSum + 4 * BN;

    const int r0 = lane >> 2;
#pragma unroll
    for (int nt = 0; nt < NT; nt++) {
        const int colLocal = nW + nt * 8 + (lane & 3) * 2;
        const float b0 = __ldg(bias + n0 + colLocal);
        const float b1 = __ldg(bias + n0 + colLocal + 1);
        float v0 = acc[0][nt][0] + b0, v1 = acc[0][nt][1] + b1;
        float v2 = acc[0][nt][2] + b0, v3 = acc[0][nt][3] + b1;
        float v4 = acc[1][nt][0] + b0, v5 = acc[1][nt][1] + b1;
        float v6 = acc[1][nt][2] + b0, v7 = acc[1][nt][3] + b1;
        if (STORE_Y) {
            if (YF32) {
                float* yf = (float*)Y;
                const size_t base = (size_t)(m0 + mW + r0) * NTOT + n0 + colLocal;
                *(float2*)(yf + base)            = make_float2(v0, v1);
                *(float2*)(yf + base +  8*NTOT)  = make_float2(v2, v3);
                *(float2*)(yf + base + 16*NTOT)  = make_float2(v4, v5);
                *(float2*)(yf + base + 24*NTOT)  = make_float2(v6, v7);
            } else {
                const size_t base = ((size_t)(m0 + mW + r0) * NTOT + n0 + colLocal) >> 1;
                const size_t rstep = (size_t)8 * NTOT >> 1;
                Y[base]             = packh2(v0, v1);
                Y[base +     rstep] = packh2(v2, v3);
                Y[base + 2 * rstep] = packh2(v4, v5);
                Y[base + 3 * rstep] = packh2(v6, v7);
            }
        }
        if (PART) {
            float s0 = v0+v2+v4+v6,              s1 = v1+v3+v5+v7;
            float q0 = v0*v0+v2*v2+v4*v4+v6*v6,  q1 = v1*v1+v3*v3+v5*v5+v7*v7;
#pragma unroll
            for (int d = 4; d < 32; d <<= 1) {
                s0 += __shfl_xor_sync(0xffffffffu, s0, d);
                s1 += __shfl_xor_sync(0xffffffffu, s1, d);
                q0 += __shfl_xor_sync(0xffffffffu, q0, d);
                q1 += __shfl_xor_sync(0xffffffffu, q1, d);
            }
            if (lane < 4) {
                sSum[wm*BN + colLocal] = s0;  sSum[wm*BN + colLocal + 1] = s1;
                sSq [wm*BN + colLocal] = q0;  sSq [wm*BN + colLocal + 1] = q1;
            }
        }
    }
    if (PART) {
        __syncthreads();
        for (int n = tid; n < BN; n += 256) {
            float s = sSum[n] + sSum[BN + n] + sSum[2*BN + n] + sSum[3*BN + n];
            float q = sSq [n] + sSq [BN + n] + sSq [2*BN + n] + sSq [3*BN + n];
            partSum[(size_t)(n0 + n) * MBLK + mb] = s;
            partSq [(size_t)(n0 + n) * MBLK + mb] = q;
        }
    }
}

// ---------------- HMMA GEMM wide: 512 threads, BN=256, single fp16 B (layer 3) ----------------
template<int KPAD, int KC, int KORIG>
__global__ void __launch_bounds__(512, 1) gemm_mma_w3(
    const uint32_t* __restrict__ A,
    const __half* __restrict__ BH,
    const float* __restrict__ bias,
    const float* __restrict__ scale, const float* __restrict__ shift,
    float* __restrict__ partSum, float* __restrict__ partSq,
    float* __restrict__ gmax, float* __restrict__ gmin)
{
    extern __shared__ __align__(16) char dyn[];
    constexpr int BN  = 256;
    constexpr int LDA = KC + 8;
    constexpr int LDB = BN + 8;
    constexpr int NCHUNK = KPAD / KC;
    __half* aS  = (__half*)dyn;
    __half* bHi = aS + 128 * LDA;

    const int tid = threadIdx.x;
    const int mb = blockIdx.x;
    const int m0 = mb * 128;

    const int wid = tid >> 5, lane = tid & 31;
    const int wm = wid >> 2, wn = wid & 3;
    const int mW = wm * 32, nW = wn * 64;
    constexpr int NT = 8;
    constexpr int KSTEPS_C = KC / 16;

    float acc[2][NT][4];
#pragma unroll
    for (int i = 0; i < 2; i++)
#pragma unroll
        for (int j = 0; j < NT; j++)
#pragma unroll
            for (int q = 0; q < 4; q++) acc[i][j][q] = 0.f;

    const uint32_t aU   = smem_u32(aS)  + (uint32_t)(mW + (lane & 15)) * (LDA * 2) + (lane >> 4) * 16;
    const uint32_t bHiU = smem_u32(bHi) + (uint32_t)(lane & 15) * (LDB * 2) + (uint32_t)nW * 2 + (lane >> 4) * 16;

    for (int ch = 0; ch < NCHUNK; ch++) {
        const int kbase = ch * KC;
        if (ch > 0) __syncthreads();

        constexpr int AIT = 128 * (KC / 2);
        for (int idx = tid; idx < AIT; idx += 512) {
            const int r  = idx / (KC / 2);
            const int p  = idx - r * (KC / 2);
            const int kl = 2 * p;
            const int kk = kbase + kl;
            const uint32_t w = A[((size_t)(m0 + r) * KORIG + kk) >> 1];
            const float2 f = __half22float2(*(const __half2*)&w);
            float v0 = fmaxf(fmaf(f.x, __ldg(scale + kk),     __ldg(shift + kk)),     0.f);
            float v1 = fmaxf(fmaf(f.y, __ldg(scale + kk + 1), __ldg(shift + kk + 1)), 0.f);
            *(uint32_t*)(aS + r * LDA + kl) = packh2(v0, v1);
        }
        constexpr int BIT = KC * (BN / 2);
        for (int idx = tid; idx < BIT; idx += 512) {
            const int k = idx / (BN / 2);
            const int n = 2 * (idx - k * (BN / 2));
            *(uint32_t*)(bHi + k * LDB + n) = *(const uint32_t*)(BH + (size_t)(kbase + k) * BN + n);
        }
        __syncthreads();

#pragma unroll
        for (int ks = 0; ks < KSTEPS_C; ks++) {
            uint32_t a0[4], a1[4];
            ldsm4(a0, aU + ks * 32);
            ldsm4(a1, aU + 16 * LDA * 2 + ks * 32);
#pragma unroll
            for (int ng = 0; ng < NT / 2; ng++) {
                uint32_t bh[4];
                const uint32_t bo = (uint32_t)ks * (16 * LDB * 2) + ng * 32;
                ldsm4t(bh, bHiU + bo);
                mma_f16(acc[0][ng*2+0], a0, bh[0], bh[1]);
                mma_f16(acc[0][ng*2+1], a0, bh[2], bh[3]);
                mma_f16(acc[1][ng*2+0], a1, bh[0], bh[1]);
                mma_f16(acc[1][ng*2+1], a1, bh[2], bh[3]);
            }
        }
    }
    __syncthreads();

    float* sSum = (float*)dyn;
    float* sSq  = sSum + 4 * BN;

#pragma unroll
    for (int nt = 0; nt < NT; nt++) {
        const int colLocal = nW + nt * 8 + (lane & 3) * 2;
        const float b0 = __ldg(bias + colLocal);
        const float b1 = __ldg(bias + colLocal + 1);
        float v0 = acc[0][nt][0] + b0, v1 = acc[0][nt][1] + b1;
        float v2 = acc[0][nt][2] + b0, v3 = acc[0][nt][3] + b1;
        float v4 = acc[1][nt][0] + b0, v5 = acc[1][nt][1] + b1;
        float v6 = acc[1][nt][2] + b0, v7 = acc[1][nt][3] + b1;
        float s0 = v0+v2+v4+v6,              s1 = v1+v3+v5+v7;
        float q0 = v0*v0+v2*v2+v4*v4+v6*v6,  q1 = v1*v1+v3*v3+v5*v5+v7*v7;
        float mx0 = fmaxf(fmaxf(v0,v2), fmaxf(v4,v6)), mx1 = fmaxf(fmaxf(v1,v3), fmaxf(v5,v7));
        float mn0 = fminf(fminf(v0,v2), fminf(v4,v6)), mn1 = fminf(fminf(v1,v3), fminf(v5,v7));
#pragma unroll
        for (int d = 4; d < 32; d <<= 1) {
            s0 += __shfl_xor_sync(0xffffffffu, s0, d);
            s1 += __shfl_xor_sync(0xffffffffu, s1, d);
            q0 += __shfl_xor_sync(0xffffffffu, q0, d);
            q1 += __shfl_xor_sync(0xffffffffu, q1, d);
            mx0 = fmaxf(mx0, __shfl_xor_sync(0xffffffffu, mx0, d));
            mx1 = fmaxf(mx1, __shfl_xor_sync(0xffffffffu, mx1, d));
            mn0 = fminf(mn0, __shfl_xor_sync(0xffffffffu, mn0, d));
            mn1 = fminf(mn1, __shfl_xor_sync(0xffffffffu, mn1, d));
        }
        if (lane < 4) {
            sSum[wm*BN + colLocal] = s0;  sSum[wm*BN + colLocal + 1] = s1;
            sSq [wm*BN + colLocal] = q0;  sSq [wm*BN + colLocal + 1] = q1;
            const size_t grp = (size_t)(mb * 4 + wm) * CH3 + colLocal;
            gmax[grp]     = mx0;  gmax[grp + 1] = mx1;
            gmin[grp]     = mn0;  gmin[grp + 1] = mn1;
        }
    }
    __syncthreads();
    for (int n = tid; n < BN; n += 512) {
        float s = sSum[n] + sSum[BN + n] + sSum[2*BN + n] + sSum[3*BN + n];
        float q = sSq [n] + sSq [BN + n] + sSq [2*BN + n] + sSq [3*BN + n];
        partSum[(size_t)n * MBLK + mb] = s;
        partSq [(size_t)n * MBLK + mb] = q;
    }
}

// ---------------- y1build ----------------
__global__ __launch_bounds__(256) void y1build_kernel(
    const float* __restrict__ G, const int* __restrict__ gidx,
    const float* __restrict__ xyz, const float* __restrict__ nxyz,
    const float* __restrict__ w0,
    uint32_t* __restrict__ y1,
    float* __restrict__ partSum, float* __restrict__ partSq)
{
    __shared__ int   sIdx[128];
    __shared__ float sCen[12];
    __shared__ float sW[192];
    __shared__ float sXn[128*3];
    __shared__ float sRed[1024];
    const int mb = blockIdx.x, m0 = mb * 128, tid = threadIdx.x;
    const int b = mb >> 8;

    if (tid < 128) sIdx[tid] = gidx[m0 + tid];
    if (tid < 12)  sCen[tid] = nxyz[(size_t)(mb * 4) * 3 + tid];
    if (tid < 192) sW[tid]   = w0[tid];
    __syncthreads();
    if (tid < 128) {
        const int g = tid >> 5;
        const int j = sIdx[tid];
        const float* xp = xyz + ((size_t)b * NPTS + j) * 3;
        sXn[tid*3+0] = xp[0] - sCen[g*3+0];
        sXn[tid*3+1] = xp[1] - sCen[g*3+1];
        sXn[tid*3+2] = xp[2] - sCen[g*3+2];
    }
    __syncthreads();

    const int cp = tid & 31;
    const int rg = tid >> 5;
    const int c0 = 2 * cp;
    const float wx0 = sW[c0],   wy0 = sW[64+c0],   wz0 = sW[128+c0];
    const float wx1 = sW[c0+1], wy1 = sW[64+c0+1], wz1 = sW[128+c0+1];

    float s0 = 0.f, s1 = 0.f, q0 = 0.f, q1 = 0.f;
#pragma unroll 4
    for (int rr = 0; rr < 16; rr++) {
        const int r = rg * 16 + rr;
        const int j = sIdx[r];
        const float xn = sXn[r*3], yn = sXn[r*3+1], zn = sXn[r*3+2];
        const float2 gv = *(const float2*)(G + ((size_t)b * NPTS + j) * CH1 + c0);
        float v0 = fmaf(zn, wz0, fmaf(yn, wy0, fmaf(xn, wx0, gv.x)));
        float v1 = fmaf(zn, wz1, fmaf(yn, wy1, fmaf(xn, wx1, gv.y)));
        y1[(size_t)(m0 + r) * (CH1/2) + cp] = packh2(v0, v1);
        s0 += v0; s1 += v1; q0 += v0*v0; q1 += v1*v1;
    }
    sRed[rg*64 + c0]       = s0;  sRed[rg*64 + c0 + 1]       = s1;
    sRed[512 + rg*64 + c0] = q0;  sRed[512 + rg*64 + c0 + 1] = q1;
    __syncthreads();
    if (rg == 0) {
        float S0 = 0.f, S1 = 0.f, Q0 = 0.f, Q1 = 0.f;
#pragma unroll
        for (int g2 = 0; g2 < 8; g2++) {
            S0 += sRed[g2*64 + c0];       S1 += sRed[g2*64 + c0 + 1];
            Q0 += sRed[512 + g2*64 + c0]; Q1 += sRed[512 + g2*64 + c0 + 1];
        }
        partSum[(size_t)c0 * MBLK + mb]       = S0;
        partSum[(size_t)(c0 + 1) * MBLK + mb] = S1;
        partSq [(size_t)c0 * MBLK + mb]       = Q0;
        partSq [(size_t)(c0 + 1) * MBLK + mb] = Q1;
    }
}

// ---------------- fold partials -> scale/shift ----------------
__global__ __launch_bounds__(256) void stats_kernel(const float* __restrict__ partSum,
                                                    const float* __restrict__ partSq,
                                                    int N,
                                                    const float* __restrict__ g,
                                                    const float* __restrict__ bt,
                                                    float* __restrict__ scale,
                                                    float* __restrict__ shift)
{
    const int c = blockIdx.x, tid = threadIdx.x;
    __shared__ float ss[256], sq[256];
    float a = 0.f, b2 = 0.f;
    const float* ps = partSum + (size_t)c * MBLK;
    const float* pq = partSq  + (size_t)c * MBLK;
    for (int mb = tid; mb < MBLK; mb += 256) {
        a  += ps[mb];
        b2 += pq[mb];
    }
    ss[tid] = a; sq[tid] = b2;
    __syncthreads();
    for (int s = 128; s > 0; s >>= 1) {
        if (tid < s) { ss[tid] += ss[tid+s]; sq[tid] += sq[tid+s]; }
        __syncthreads();
    }
    if (tid == 0) {
        const float invM = 1.0f / (float)MTOT;
        float mean = ss[0] * invM;
        float var  = sq[0] * invM - mean * mean;
        float sc   = g[c] / sqrtf(var + BNEPS);
        scale[c] = sc;
        shift[c] = bt[c] - mean * sc;
    }
}

// ---------------- final pool ----------------
__global__ __launch_bounds__(256) void finalpool_kernel(const float* __restrict__ gmax,
                                                        const float* __restrict__ gmin,
                                                        const float* __restrict__ scale,
                                                        const float* __restrict__ shift,
                                                        float* __restrict__ out)
{
    const int g = blockIdx.x, c = threadIdx.x;
    const float sc = scale[c], sh = shift[c];
    const float v = (sc >= 0.f) ? gmax[(size_t)g * CH3 + c] : gmin[(size_t)g * CH3 + c];
    out[(size_t)g * CH3 + c] = fmaxf(fmaf(v, sc, sh), 0.f);
}

// ---------------- launch ----------------
extern "C" void kernel_launch(void* const* d_in, const int* in_sizes, int n_in,
                              void* d_out, int out_size)
{
    const float* xyz    = (const float*)d_in[0];
    const float* points = (const float*)d_in[1];
    const float* w0  = (const float*)d_in[2];
    const float* b0  = (const float*)d_in[3];
    const float* g0  = (const float*)d_in[4];
    const float* bt0 = (const float*)d_in[5];
    const float* w1  = (const float*)d_in[6];
    const float* b1  = (const float*)d_in[7];
    const float* g1  = (const float*)d_in[8];
    const float* bt1 = (const float*)d_in[9];
    const float* w2  = (const float*)d_in[10];
    const float* b2  = (const float*)d_in[11];
    const float* g2  = (const float*)d_in[12];
    const float* bt2 = (const float*)d_in[13];

    float* out        = (float*)d_out;
    float* new_xyz    = out;
    float* new_points = out + (size_t)BATCH*SPTS*3;

    float *Gp, *part, *scale, *shift, *gmax, *gmin;
    uint32_t *y1, *y2;
    int* gidx;
    __half *bh0, *bl0, *bh1, *bl1, *bh2, *bl2;
    cudaGetSymbolAddress((void**)&Gp,    g_G);
    cudaGetSymbolAddress((void**)&y1,    g_y1);
    cudaGetSymbolAddress((void**)&y2,    g_y2);
    cudaGetSymbolAddress((void**)&part,  g_part);
    cudaGetSymbolAddress((void**)&scale, g_scale);
    cudaGetSymbolAddress((void**)&shift, g_shift);
    cudaGetSymbolAddress((void**)&gidx,  g_gidx);
    cudaGetSymbolAddress((void**)&gmax,  g_gmax);
    cudaGetSymbolAddress((void**)&gmin,  g_gmin);
    cudaGetSymbolAddress((void**)&bh0,   g_bh0);
    cudaGetSymbolAddress((void**)&bl0,   g_bl0);
    cudaGetSymbolAddress((void**)&bh1,   g_bh1);
    cudaGetSymbolAddress((void**)&bl1,   g_bl1);
    cudaGetSymbolAddress((void**)&bh2,   g_bh2);
    cudaGetSymbolAddress((void**)&bl2,   g_bl2);

    float* partSum = part;
    float* partSq  = part + (size_t)MBLK * CH3;

    constexpr int SMG = (128*(64+8) + 2*64*(64+8))  * 2;   //  36,864 (B split)
    constexpr int SM2 = (128*(64+8) + 64*(128+8))   * 2;   //  35,840 (single B)
    constexpr int SMW = (128*(64+8) + 64*(256+8))   * 2;   //  52,224 (single B)

    static bool attrDone = false;
    if (!attrDone) {
        cudaFuncSetAttribute(gemm_mma<64, 64, 64, 64, 64, 2, true, false, true, true, false, 2>,
                             cudaFuncAttributeMaxDynamicSharedMemorySize, SMG);
        cudaFuncSetAttribute(gemm_mma<128, 128, 64, 64, 64, 1, false, true, true, false, true, 3>,
                             cudaFuncAttributeMaxDynamicSharedMemorySize, SM2);
        cudaFuncSetAttribute(gemm_mma_w3<128, 64, 128>,
                             cudaFuncAttributeMaxDynamicSharedMemorySize, SMW);
        attrDone = true;
    }

    prep_kernel<<<(64*64 + 255)/256, 256>>>(w0, 64, CH1, 64, 3, bh0, bl0);
    prep_kernel<<<(64*128 + 255)/256, 256>>>(w1, CH1, CH2, 64, 0, bh1, bl1);
    prep_kernel<<<(128*256 + 255)/256, 256>>>(w2, CH2, CH3, 128, 0, bh2, bl2);

    // G = points . W0[3:67] + b0  (B-split kept: error at the source stays small)
    gemm_mma<64, 64, 64, 64, 64, 2, true, false, true, true, false, 2><<<dim3(1, 512), 256, SMG>>>(
        nullptr, points, bh0, bl0, b0, nullptr, nullptr, (uint32_t*)Gp, nullptr, nullptr);

    fps_kernel<<<BATCH, 512>>>(xyz, new_xyz);
    ballquery_kernel<<<BATCH*SPTS/8, 256>>>(xyz, new_xyz, gidx);

    y1build_kernel<<<MBLK, 256>>>(Gp, gidx, xyz, new_xyz, w0, y1, partSum, partSq);
    stats_kernel<<<CH1, 256>>>(partSum, partSq, CH1, g0, bt0, scale, shift);

    // layer 2: 64 -> 128, single fp16 B, 3 CTAs/SM
    gemm_mma<128, 128, 64, 64, 64, 1, false, true, true, false, true, 3><<<dim3(1, MBLK), 256, SM2>>>(
        y1, nullptr, bh1, bl1, b1, scale, shift, y2, partSum, partSq);
    stats_kernel<<<CH2, 256>>>(partSum, partSq, CH2, g1, bt1, scale, shift);

    // layer 3: 128 -> 256 wide CTA, single fp16 B
    gemm_mma_w3<128, 64, 128><<<MBLK, 512, SMW>>>(
        y2, bh2, b2, scale, shift, partSum, partSq, gmax, gmin);
    stats_kernel<<<CH3, 256>>>(partSum, partSq, CH3, g2, bt2, scale, shift);

    finalpool_kernel<<<BATCH*SPTS, 256>>>(gmax, gmin, scale, shift, new_points);
}

// round 16
// speedup vs baseline: 1.2183x; 1.0144x over previous
#include <cuda_runtime.h>
#include <cuda_fp16.h>
#include <math.h>
#include <stdint.h>

// ---------------- problem constants ----------------
#define BATCH 16
#define NPTS  4096
#define DFEAT 64
#define SPTS  1024
#define NSAMP 32
#define CH0   67
#define CH1   64
#define CH2   128
#define CH3   256
#define MTOT  (BATCH*SPTS*NSAMP)   // 524288
#define MBLK  (MTOT/128)           // 4096
#define RAD2  0.04f
#define BNEPS 1e-5f

typedef unsigned long long ull;

// ---------------- device scratch ----------------
__device__ float    g_G[(size_t)BATCH*NPTS*CH1];
__device__ uint32_t g_y1[(size_t)MTOT*CH1/2];      // fp16 pairs
__device__ uint32_t g_y2[(size_t)MTOT*CH2/2];      // fp16 pairs
__device__ int   g_gidx[BATCH*SPTS*NSAMP];
__device__ float g_part[2*(size_t)MBLK*CH3];       // transposed [n][MBLK]
__device__ float g_scale[CH3];
__device__ float g_shift[CH3];
__device__ float g_gmax[(size_t)BATCH*SPTS*CH3];
__device__ float g_gmin[(size_t)BATCH*SPTS*CH3];
__device__ __half g_bh0[64*64],   g_bl0[64*64];
__device__ __half g_bh1[64*128],  g_bl1[64*128];
__device__ __half g_bh2[128*256], g_bl2[128*256];

// ---------------- helpers ----------------
__device__ __forceinline__ uint32_t smem_u32(const void* p) {
    uint32_t a;
    asm("{ .reg .u64 t; cvta.to.shared.u64 t, %1; cvt.u32.u64 %0, t; }" : "=r"(a) : "l"(p));
    return a;
}
__device__ __forceinline__ void ldsm4(uint32_t* r, uint32_t a) {
    asm volatile("ldmatrix.sync.aligned.m8n8.x4.shared.b16 {%0,%1,%2,%3}, [%4];"
                 : "=r"(r[0]), "=r"(r[1]), "=r"(r[2]), "=r"(r[3]) : "r"(a));
}
__device__ __forceinline__ void ldsm4t(uint32_t* r, uint32_t a) {
    asm volatile("ldmatrix.sync.aligned.m8n8.x4.trans.shared.b16 {%0,%1,%2,%3}, [%4];"
                 : "=r"(r[0]), "=r"(r[1]), "=r"(r[2]), "=r"(r[3]) : "r"(a));
}
__device__ __forceinline__ void mma_f16(float* c, const uint32_t* a, uint32_t b0, uint32_t b1) {
    asm volatile(
        "mma.sync.aligned.m16n8k16.row.col.f32.f16.f16.f32 "
        "{%0,%1,%2,%3}, {%4,%5,%6,%7}, {%8,%9}, {%0,%1,%2,%3};"
        : "+f"(c[0]), "+f"(c[1]), "+f"(c[2]), "+f"(c[3])
        : "r"(a[0]), "r"(a[1]), "r"(a[2]), "r"(a[3]), "r"(b0), "r"(b1));
}
__device__ __forceinline__ uint32_t packh2(float v0, float v1) {
    __half2 h = __floats2half2_rn(v0, v1);
    return *(uint32_t*)&h;
}

// ---------------- fused FPS + G-GEMM ----------------
// bid 0..15: FPS (one block per batch). bid 16..527: G = points.W0[3:67]+b0, mb=bid-16.
__global__ __launch_bounds__(512, 2) void fpsg_kernel(
    const float* __restrict__ xyz, float* __restrict__ new_xyz,
    const float* __restrict__ points,
    const __half* __restrict__ BH, const __half* __restrict__ BL,
    const float* __restrict__ bias,
    float* __restrict__ G)
{
    extern __shared__ __align__(16) char dyn[];
    const int tid = threadIdx.x;
    const int lane = tid & 31, wid = tid >> 5;

    if (blockIdx.x < 16) {
        // ================= FPS =================
        float* sx = (float*)dyn;
        float* sy = sx + NPTS;
        float* sz = sy + NPTS;
        __shared__ unsigned s_val[2][16], s_low[2][16];
        const int b = blockIdx.x;
        const float* X = xyz + (size_t)b * NPTS * 3;

        ull pxp[4], pyp[4], pzp[4];
        float dist[8];
#pragma unroll
        for (int t = 0; t < 8; t++) dist[t] = 1e10f;
#pragma unroll
        for (int t = 0; t < 4; t++) {
            const int j0 = tid + (2*t) * 512, j1 = tid + (2*t+1) * 512;
            float x0 = X[3*j0], y0 = X[3*j0+1], z0 = X[3*j0+2];
            float x1 = X[3*j1], y1 = X[3*j1+1], z1 = X[3*j1+2];
            sx[j0] = x0; sy[j0] = y0; sz[j0] = z0;
            sx[j1] = x1; sy[j1] = y1; sz[j1] = z1;
            asm("mov.b64 %0, {%1,%2};" : "=l"(pxp[t]) : "f"(x0), "f"(x1));
            asm("mov.b64 %0, {%1,%2};" : "=l"(pyp[t]) : "f"(y0), "f"(y1));
            asm("mov.b64 %0, {%1,%2};" : "=l"(pzp[t]) : "f"(z0), "f"(z1));
        }
        __syncthreads();

        int far = 0;
        for (int i = 0; i < SPTS; i++) {
            const float cx = sx[far], cy = sy[far], cz = sz[far];
            if (tid == 0) {
                float* o = new_xyz + ((size_t)b * SPTS + i) * 3;
                o[0] = cx; o[1] = cy; o[2] = cz;
            }
            if (i == SPTS - 1) break;

            const float mx = -cx, my = -cy, mz = -cz;
            ull ncx, ncy, ncz;
            asm("mov.b64 %0, {%1,%1};" : "=l"(ncx) : "f"(mx));
            asm("mov.b64 %0, {%1,%1};" : "=l"(ncy) : "f"(my));
            asm("mov.b64 %0, {%1,%1};" : "=l"(ncz) : "f"(mz));

            float bv = -1.0f; int bi = 0;
#pragma unroll
            for (int t = 0; t < 4; t++) {
                ull dx, dy, dz, dd;
                asm("add.rn.f32x2 %0, %1, %2;" : "=l"(dx) : "l"(pxp[t]), "l"(ncx));
                asm("add.rn.f32x2 %0, %1, %2;" : "=l"(dy) : "l"(pyp[t]), "l"(ncy));
                asm("add.rn.f32x2 %0, %1, %2;" : "=l"(dz) : "l"(pzp[t]), "l"(ncz));
                asm("mul.rn.f32x2 %0, %1, %2;" : "=l"(dd) : "l"(dx), "l"(dx));
                asm("fma.rn.f32x2 %0, %1, %2, %3;" : "=l"(dd) : "l"(dy), "l"(dy), "l"(dd));
                asm("fma.rn.f32x2 %0, %1, %2, %3;" : "=l"(dd) : "l"(dz), "l"(dz), "l"(dd));
                float d0, d1;
                asm("mov.b64 {%0,%1}, %2;" : "=f"(d0), "=f"(d1) : "l"(dd));
                const float nd0 = fminf(dist[2*t],   d0);
                const float nd1 = fminf(dist[2*t+1], d1);
                dist[2*t]   = nd0;
                dist[2*t+1] = nd1;
                if (nd0 > bv) { bv = nd0; bi = tid + (2*t)   * 512; }
                if (nd1 > bv) { bv = nd1; bi = tid + (2*t+1) * 512; }
            }
            const unsigned vb = __float_as_uint(bv);
            const unsigned m  = __reduce_max_sync(0xffffffffu, vb);
            const unsigned lw = __reduce_max_sync(0xffffffffu,
                                                  (vb == m) ? (0xFFFFu - (unsigned)bi) : 0u);
            const int buf = i & 1;
            if (lane == 0) { s_val[buf][wid] = m; s_low[buf][wid] = lw; }
            __syncthreads();

            const unsigned v2 = s_val[buf][lane & 15];
            const unsigned l2 = s_low[buf][lane & 15];
            const unsigned M  = __reduce_max_sync(0xffffffffu, v2);
            const unsigned LW = __reduce_max_sync(0xffffffffu, (v2 == M) ? l2 : 0u);
            far = 0xFFFF - (int)LW;
        }
        return;
    }

    // ================= G-GEMM (512 threads, 16 warps 4x4, B split) =================
    constexpr int BN = 64, K = 64;
    constexpr int LDA = K + 8, LDB = BN + 8;
    __half* aS  = (__half*)dyn;
    __half* bHi = aS + 128 * LDA;
    __half* bLo = bHi + K * LDB;

    const int mb = blockIdx.x - 16;
    const int m0 = mb * 128;
    const int wm = wid >> 2, wn = wid & 3;
    const int mW = wm * 32, nW = wn * 16;

    float acc[2][2][4];
#pragma unroll
    for (int i = 0; i < 2; i++)
#pragma unroll
        for (int j = 0; j < 2; j++)
#pragma unroll
            for (int q = 0; q < 4; q++) acc[i][j][q] = 0.f;

    for (int idx = tid; idx < 128 * (K/2); idx += 512) {
        const int r = idx / (K/2);
        const int kl = 2 * (idx - r * (K/2));
        const float2 f = *(const float2*)(points + (size_t)(m0 + r) * K + kl);
        *(uint32_t*)(aS + r * LDA + kl) = packh2(f.x, f.y);
    }
    for (int idx = tid; idx < K * (BN/2); idx += 512) {
        const int k = idx / (BN/2);
        const int n = 2 * (idx - k * (BN/2));
        *(uint32_t*)(bHi + k * LDB + n) = *(const uint32_t*)(BH + (size_t)k * BN + n);
        *(uint32_t*)(bLo + k * LDB + n) = *(const uint32_t*)(BL + (size_t)k * BN + n);
    }
    __syncthreads();

    const uint32_t aU   = smem_u32(aS)  + (uint32_t)(mW + (lane & 15)) * (LDA * 2) + (lane >> 4) * 16;
    const uint32_t bHiU = smem_u32(bHi) + (uint32_t)(lane & 15) * (LDB * 2) + (uint32_t)nW * 2 + (lane >> 4) * 16;
    const uint32_t bLoU = smem_u32(bLo) + (uint32_t)(lane & 15) * (LDB * 2) + (uint32_t)nW * 2 + (lane >> 4) * 16;

#pragma unroll
    for (int ks = 0; ks < K/16; ks++) {
        uint32_t a0[4], a1[4], bh[4], bl[4];
        ldsm4(a0, aU + ks * 32);
        ldsm4(a1, aU + 16 * LDA * 2 + ks * 32);
        const uint32_t bo = (uint32_t)ks * (16 * LDB * 2);
        ldsm4t(bh, bHiU + bo);
        ldsm4t(bl, bLoU + bo);
        mma_f16(acc[0][0], a0, bh[0], bh[1]);
        mma_f16(acc[0][1], a0, bh[2], bh[3]);
        mma_f16(acc[1][0], a1, bh[0], bh[1]);
        mma_f16(acc[1][1], a1, bh[2], bh[3]);
        mma_f16(acc[0][0], a0, bl[0], bl[1]);
        mma_f16(acc[0][1], a0, bl[2], bl[3]);
        mma_f16(acc[1][0], a1, bl[0], bl[1]);
        mma_f16(acc[1][1], a1, bl[2], bl[3]);
    }

    const int r0 = lane >> 2;
#pragma unroll
    for (int nt = 0; nt < 2; nt++) {
        const int colLocal = nW + nt * 8 + (lane & 3) * 2;
        const float b0v = __ldg(bias + colLocal);
        const float b1v = __ldg(bias + colLocal + 1);
        const size_t base = (size_t)(m0 + mW + r0) * BN + colLocal;
        *(float2*)(G + base)          = make_float2(acc[0][nt][0] + b0v, acc[0][nt][1] + b1v);
        *(float2*)(G + base +  8*BN)  = make_float2(acc[0][nt][2] + b0v, acc[0][nt][3] + b1v);
        *(float2*)(G + base + 16*BN)  = make_float2(acc[1][nt][0] + b0v, acc[1][nt][1] + b1v);
        *(float2*)(G + base + 24*BN)  = make_float2(acc[1][nt][2] + b0v, acc[1][nt][3] + b1v);
    }
}

// ---------------- ball query ----------------
__global__ __launch_bounds__(256) void ballquery_kernel(const float* __restrict__ xyz,
                                                        const float* __restrict__ new_xyz,
                                                        int* __restrict__ gidx)
{
    const int w    = blockIdx.x * 8 + (threadIdx.x >> 5);
    const int lane = threadIdx.x & 31;
    const int b    = w >> 10;
    const float* X = xyz + (size_t)b * NPTS * 3;

    const float cx = new_xyz[(size_t)w*3+0];
    const float cy = new_xyz[(size_t)w*3+1];
    const float cz = new_xyz[(size_t)w*3+2];
    const float ss = cx*cx + cy*cy + cz*cz;

    int cnt = 0, firstIdx = 0;
    int* out = gidx + (size_t)w * NSAMP;

    for (int base = 0; base < NPTS && cnt < NSAMP; base += 32) {
        const int j = base + lane;
        const float x = X[3*j], y = X[3*j+1], z = X[3*j+2];
        const float pp  = x*x + y*y + z*z;
        const float dot = x*cx + y*cy + z*cz;
        const float d   = (-2.0f*dot + ss) + pp;
        const bool  in  = !(d > RAD2);
        unsigned mask = __ballot_sync(0xffffffffu, in);
        if (cnt == 0 && mask) firstIdx = base + (__ffs(mask) - 1);
        int rank = __popc(mask & ((1u << lane) - 1u));
        int slot = cnt + rank;
        if (in && slot < NSAMP) out[slot] = j;
        cnt += __popc(mask);
    }
    for (int t = cnt + lane; t < NSAMP; t += 32) out[t] = firstIdx;
}

// ---------------- weight prep ----------------
__global__ __launch_bounds__(256) void prep_kernel(const float* __restrict__ W, int K, int N,
                                                   int KPAD, int KOFF,
                                                   __half* __restrict__ bh,
                                                   __half* __restrict__ bl)
{
    int i = blockIdx.x * 256 + threadIdx.x;
    if (i >= N * KPAD) return;
    int k = i / N, n = i - k * N;
    float v = (k < K) ? W[(size_t)(k + KOFF) * N + n] : 0.f;
    __half h = __float2half_rn(v);
    bh[i] = h;
    bl[i] = __float2half_rn(v - __half2float(h));
}

// ---------------- HMMA GEMM, 256 threads (layers 2 & 3) ----------------
template<int BN, int NTOT, int KPAD, int KC, int KORIG,
         bool STORE_Y, bool FMAX, int MINB>
__global__ void __launch_bounds__(256, MINB) gemm_mma(
    const uint32_t* __restrict__ A,
    const __half* __restrict__ BH,
    const float* __restrict__ bias,
    const float* __restrict__ scale, const float* __restrict__ shift,
    uint32_t* __restrict__ Y,
    float* __restrict__ partSum, float* __restrict__ partSq,
    float* __restrict__ gmax, float* __restrict__ gmin)
{
    extern __shared__ __align__(16) char dyn[];
    constexpr int LDA = KC + 8;
    constexpr int LDB = BN + 8;
    constexpr int NCHUNK = KPAD / KC;
    __half* aS  = (__half*)dyn;
    __half* bHi = aS + 128 * LDA;

    const int tid = threadIdx.x;
    const int nb = blockIdx.x, mb = blockIdx.y;
    const int m0 = mb * 128, n0 = nb * BN;

    const int wid = tid >> 5, lane = tid & 31;
    const int wm = wid >> 1, wn = wid & 1;
    const int mW = wm * 32, nW = wn * (BN / 2);
    constexpr int NT = BN / 16;
    constexpr int KSTEPS_C = KC / 16;

    float acc[2][NT][4];
#pragma unroll
    for (int i = 0; i < 2; i++)
#pragma unroll
        for (int j = 0; j < NT; j++)
#pragma unroll
            for (int q = 0; q < 4; q++) acc[i][j][q] = 0.f;

    const uint32_t aU   = smem_u32(aS)  + (uint32_t)(mW + (lane & 15)) * (LDA * 2) + (lane >> 4) * 16;
    const uint32_t bHiU = smem_u32(bHi) + (uint32_t)(lane & 15) * (LDB * 2) + (uint32_t)nW * 2 + (lane >> 4) * 16;

    for (int ch = 0; ch < NCHUNK; ch++) {
        const int kbase = ch * KC;
        if (ch > 0) __syncthreads();

        constexpr int AIT = 128 * (KC / 2);
        for (int idx = tid; idx < AIT; idx += 256) {
            const int r  = idx / (KC / 2);
            const int p  = idx - r * (KC / 2);
            const int kl = 2 * p;
            const int kk = kbase + kl;
            const uint32_t w = A[((size_t)(m0 + r) * KORIG + kk) >> 1];
            const float2 f = __half22float2(*(const __half2*)&w);
            float v0 = fmaxf(fmaf(f.x, __ldg(scale + kk),     __ldg(shift + kk)),     0.f);
            float v1 = fmaxf(fmaf(f.y, __ldg(scale + kk + 1), __ldg(shift + kk + 1)), 0.f);
            *(uint32_t*)(aS + r * LDA + kl) = packh2(v0, v1);
        }
        constexpr int BIT = KC * (BN / 2);
        for (int idx = tid; idx < BIT; idx += 256) {
            const int k = idx / (BN / 2);
            const int n = 2 * (idx - k * (BN / 2));
            *(uint32_t*)(bHi + k * LDB + n) = *(const uint32_t*)(BH + (size_t)(kbase + k) * NTOT + n0 + n);
        }
        __syncthreads();

#pragma unroll
        for (int ks = 0; ks < KSTEPS_C; ks++) {
            uint32_t a0[4], a1[4];
            ldsm4(a0, aU + ks * 32);
            ldsm4(a1, aU + 16 * LDA * 2 + ks * 32);
#pragma unroll
            for (int ng = 0; ng < NT / 2; ng++) {
                uint32_t bh[4];
                const uint32_t bo = (uint32_t)ks * (16 * LDB * 2) + ng * 32;
                ldsm4t(bh, bHiU + bo);
                mma_f16(acc[0][ng*2+0], a0, bh[0], bh[1]);
                mma_f16(acc[0][ng*2+1], a0, bh[2], bh[3]);
                mma_f16(acc[1][ng*2+0], a1, bh[0], bh[1]);
                mma_f16(acc[1][ng*2+1], a1, bh[2], bh[3]);
            }
        }
    }
    __syncthreads();

    float* sSum = (float*)dyn;            // [4][BN]
    float* sSq  = sSum + 4 * BN;

    const int r0 = lane >> 2;
#pragma unroll
    for (int nt = 0; nt < NT; nt++) {
        const int colLocal = nW + nt * 8 + (lane & 3) * 2;
        const float b0 = __ldg(bias + n0 + colLocal);
        const float b1 = __ldg(bias + n0 + colLocal + 1);
        float v0 = acc[0][nt][0] + b0, v1 = acc[0][nt][1] + b1;
        float v2 = acc[0][nt][2] + b0, v3 = acc[0][nt][3] + b1;
        float v4 = acc[1][nt][0] + b0, v5 = acc[1][nt][1] + b1;
        float v6 = acc[1][nt][2] + b0, v7 = acc[1][nt][3] + b1;
        if (STORE_Y) {
            const size_t base = ((size_t)(m0 + mW + r0) * NTOT + n0 + colLocal) >> 1;
            const size_t rstep = (size_t)8 * NTOT >> 1;
            Y[base]             = packh2(v0, v1);
            Y[base +     rstep] = packh2(v2, v3);
            Y[base + 2 * rstep] = packh2(v4, v5);
            Y[base + 3 * rstep] = packh2(v6, v7);
        }
        float s0 = v0+v2+v4+v6,              s1 = v1+v3+v5+v7;
        float q0 = v0*v0+v2*v2+v4*v4+v6*v6,  q1 = v1*v1+v3*v3+v5*v5+v7*v7;
        float mx0, mx1, mn0, mn1;
        if (FMAX) {
            mx0 = fmaxf(fmaxf(v0,v2), fmaxf(v4,v6)); mx1 = fmaxf(fmaxf(v1,v3), fmaxf(v5,v7));
            mn0 = fminf(fminf(v0,v2), fminf(v4,v6)); mn1 = fminf(fminf(v1,v3), fminf(v5,v7));
        }
#pragma unroll
        for (int d = 4; d < 32; d <<= 1) {
            s0 += __shfl_xor_sync(0xffffffffu, s0, d);
            s1 += __shfl_xor_sync(0xffffffffu, s1, d);
            q0 += __shfl_xor_sync(0xffffffffu, q0, d);
            q1 += __shfl_xor_sync(0xffffffffu, q1, d);
            if (FMAX) {
                mx0 = fmaxf(mx0, __shfl_xor_sync(0xffffffffu, mx0, d));
                mx1 = fmaxf(mx1, __shfl_xor_sync(0xffffffffu, mx1, d));
                mn0 = fminf(mn0, __shfl_xor_sync(0xffffffffu, mn0, d));
                mn1 = fminf(mn1, __shfl_xor_sync(0xffffffffu, mn1, d));
            }
        }
        if (lane < 4) {
            sSum[wm*BN + colLocal] = s0;  sSum[wm*BN + colLocal + 1] = s1;
            sSq [wm*BN + colLocal] = q0;  sSq [wm*BN + colLocal + 1] = q1;
            if (FMAX) {
                const size_t grp = (size_t)(mb * 4 + wm) * CH3 + n0 + colLocal;
                gmax[grp]     = mx0;  gmax[grp + 1] = mx1;
                gmin[grp]     = mn0;  gmin[grp + 1] = mn1;
            }
        }
    }
    __syncthreads();
    for (int n = tid; n < BN; n += 256) {
        float s = sSum[n] + sSum[BN + n] + sSum[2*BN + n] + sSum[3*BN + n];
        float q = sSq [n] + sSq [BN + n] + sSq [2*BN + n] + sSq [3*BN + n];
        partSum[(size_t)(n0 + n) * MBLK + mb] = s;
        partSq [(size_t)(n0 + n) * MBLK + mb] = q;
    }
}

// ---------------- y1build ----------------
__global__ __launch_bounds__(256) void y1build_kernel(
    const float* __restrict__ G, const int* __restrict__ gidx,
    const float* __restrict__ xyz, const float* __restrict__ nxyz,
    const float* __restrict__ w0,
    uint32_t* __restrict__ y1,
    float* __restrict__ partSum, float* __restrict__ partSq)
{
    __shared__ int   sIdx[128];
    __shared__ float sCen[12];
    __shared__ float sW[192];
    __shared__ float sXn[128*3];
    __shared__ float sRed[1024];
    const int mb = blockIdx.x, m0 = mb * 128, tid = threadIdx.x;
    const int b = mb >> 8;

    if (tid < 128) sIdx[tid] = gidx[m0 + tid];
    if (tid < 12)  sCen[tid] = nxyz[(size_t)(mb * 4) * 3 + tid];
    if (tid < 192) sW[tid]   = w0[tid];
    __syncthreads();
    if (tid < 128) {
        const int g = tid >> 5;
        const int j = sIdx[tid];
        const float* xp = xyz + ((size_t)b * NPTS + j) * 3;
        sXn[tid*3+0] = xp[0] - sCen[g*3+0];
        sXn[tid*3+1] = xp[1] - sCen[g*3+1];
        sXn[tid*3+2] = xp[2] - sCen[g*3+2];
    }
    __syncthreads();

    const int cp = tid & 31;
    const int rg = tid >> 5;
    const int c0 = 2 * cp;
    const float wx0 = sW[c0],   wy0 = sW[64+c0],   wz0 = sW[128+c0];
    const float wx1 = sW[c0+1], wy1 = sW[64+c0+1], wz1 = sW[128+c0+1];

    float s0 = 0.f, s1 = 0.f, q0 = 0.f, q1 = 0.f;
#pragma unroll 4
    for (int rr = 0; rr < 16; rr++) {
        const int r = rg * 16 + rr;
        const int j = sIdx[r];
        const float xn = sXn[r*3], yn = sXn[r*3+1], zn = sXn[r*3+2];
        const float2 gv = *(const float2*)(G + ((size_t)b * NPTS + j) * CH1 + c0);
        float v0 = fmaf(zn, wz0, fmaf(yn, wy0, fmaf(xn, wx0, gv.x)));
        float v1 = fmaf(zn, wz1, fmaf(yn, wy1, fmaf(xn, wx1, gv.y)));
        y1[(size_t)(m0 + r) * (CH1/2) + cp] = packh2(v0, v1);
        s0 += v0; s1 += v1; q0 += v0*v0; q1 += v1*v1;
    }
    sRed[rg*64 + c0]       = s0;  sRed[rg*64 + c0 + 1]       = s1;
    sRed[512 + rg*64 + c0] = q0;  sRed[512 + rg*64 + c0 + 1] = q1;
    __syncthreads();
    if (rg == 0) {
        float S0 = 0.f, S1 = 0.f, Q0 = 0.f, Q1 = 0.f;
#pragma unroll
        for (int g2 = 0; g2 < 8; g2++) {
            S0 += sRed[g2*64 + c0];       S1 += sRed[g2*64 + c0 + 1];
            Q0 += sRed[512 + g2*64 + c0]; Q1 += sRed[512 + g2*64 + c0 + 1];
        }
        partSum[(size_t)c0 * MBLK + mb]       = S0;
        partSum[(size_t)(c0 + 1) * MBLK + mb] = S1;
        partSq [(size_t)c0 * MBLK + mb]       = Q0;
        partSq [(size_t)(c0 + 1) * MBLK + mb] = Q1;
    }
}

// ---------------- fold partials -> scale/shift ----------------
__global__ __launch_bounds__(256) void stats_kernel(const float* __restrict__ partSum,
                                                    const float* __restrict__ partSq,
                                                    int N,
                                                    const float* __restrict__ g,
                                                    const float* __restrict__ bt,
                                                    float* __restrict__ scale,
                                                    float* __restrict__ shift)
{
    const int c = blockIdx.x, tid = threadIdx.x;
    __shared__ float ss[256], sq[256];
    float a = 0.f, b2 = 0.f;
    const float* ps = partSum + (size_t)c * MBLK;
    const float* pq = partSq  + (size_t)c * MBLK;
    for (int mb = tid; mb < MBLK; mb += 256) {
        a  += ps[mb];
        b2 += pq[mb];
    }
    ss[tid] = a; sq[tid] = b2;
    __syncthreads();
    for (int s = 128; s > 0; s >>= 1) {
        if (tid < s) { ss[tid] += ss[tid+s]; sq[tid] += sq[tid+s]; }
        __syncthreads();
    }
    if (tid == 0) {
        const float invM = 1.0f / (float)MTOT;
        float mean = ss[0] * invM;
        float var  = sq[0] * invM - mean * mean;
        float sc   = g[c] / sqrtf(var + BNEPS);
        scale[c] = sc;
        shift[c] = bt[c] - mean * sc;
    }
}

// ---------------- final pool ----------------
__global__ __launch_bounds__(256) void finalpool_kernel(const float* __restrict__ gmax,
                                                        const float* __restrict__ gmin,
                                                        const float* __restrict__ scale,
                                                        const float* __restrict__ shift,
                                                        float* __restrict__ out)
{
    const int g = blockIdx.x, c = threadIdx.x;
    const float sc = scale[c], sh = shift[c];
    const float v = (sc >= 0.f) ? gmax[(size_t)g * CH3 + c] : gmin[(size_t)g * CH3 + c];
    out[(size_t)g * CH3 + c] = fmaxf(fmaf(v, sc, sh), 0.f);
}

// ---------------- launch ----------------
extern "C" void kernel_launch(void* const* d_in, const int* in_sizes, int n_in,
                              void* d_out, int out_size)
{
    const float* xyz    = (const float*)d_in[0];
    const float* points = (const float*)d_in[1];
    const float* w0  = (const float*)d_in[2];
    const float* b0  = (const float*)d_in[3];
    const float* g0  = (const float*)d_in[4];
    const float* bt0 = (const float*)d_in[5];
    const float* w1  = (const float*)d_in[6];
    const float* b1  = (const float*)d_in[7];
    const float* g1  = (const float*)d_in[8];
    const float* bt1 = (const float*)d_in[9];
    const float* w2  = (const float*)d_in[10];
    const float* b2  = (const float*)d_in[11];
    const float* g2  = (const float*)d_in[12];
    const float* bt2 = (const float*)d_in[13];

    float* out        = (float*)d_out;
    float* new_xyz    = out;
    float* new_points = out + (size_t)BATCH*SPTS*3;

    float *Gp, *part, *scale, *shift, *gmax, *gmin;
    uint32_t *y1, *y2;
    int* gidx;
    __half *bh0, *bl0, *bh1, *bl1, *bh2, *bl2;
    cudaGetSymbolAddress((void**)&Gp,    g_G);
    cudaGetSymbolAddress((void**)&y1,    g_y1);
    cudaGetSymbolAddress((void**)&y2,    g_y2);
    cudaGetSymbolAddress((void**)&part,  g_part);
    cudaGetSymbolAddress((void**)&scale, g_scale);
    cudaGetSymbolAddress((void**)&shift, g_shift);
    cudaGetSymbolAddress((void**)&gidx,  g_gidx);
    cudaGetSymbolAddress((void**)&gmax,  g_gmax);
    cudaGetSymbolAddress((void**)&gmin,  g_gmin);
    cudaGetSymbolAddress((void**)&bh0,   g_bh0);
    cudaGetSymbolAddress((void**)&bl0,   g_bl0);
    cudaGetSymbolAddress((void**)&bh1,   g_bh1);
    cudaGetSymbolAddress((void**)&bl1,   g_bl1);
    cudaGetSymbolAddress((void**)&bh2,   g_bh2);
    cudaGetSymbolAddress((void**)&bl2,   g_bl2);

    float* partSum = part;
    float* partSq  = part + (size_t)MBLK * CH3;

    constexpr int SMF = 3 * NPTS * 4;                    // 49,152 (FPS cache; G fits inside)
    constexpr int SM2 = (128*(64+8) + 64*(128+8)) * 2;   // 35,840
    constexpr int SMW = SM2;                             // layer 3 uses same shape

    static bool attrDone = false;
    if (!attrDone) {
        cudaFuncSetAttribute(fpsg_kernel,
                             cudaFuncAttributeMaxDynamicSharedMemorySize, SMF);
        cudaFuncSetAttribute(gemm_mma<128, 128, 64, 64, 64, true, false, 3>,
                             cudaFuncAttributeMaxDynamicSharedMemorySize, SM2);
        cudaFuncSetAttribute(gemm_mma<128, 256, 128, 64, 128, false, true, 3>,
                             cudaFuncAttributeMaxDynamicSharedMemorySize, SMW);
        attrDone = true;
    }

    prep_kernel<<<(64*64 + 255)/256, 256>>>(w0, 64, CH1, 64, 3, bh0, bl0);
    prep_kernel<<<(64*128 + 255)/256, 256>>>(w1, CH1, CH2, 64, 0, bh1, bl1);
    prep_kernel<<<(128*256 + 255)/256, 256>>>(w2, CH2, CH3, 128, 0, bh2, bl2);

    // fused: FPS (16 CTAs) + G-GEMM (512 CTAs) run concurrently
    fpsg_kernel<<<16 + 512, 512, SMF>>>(xyz, new_xyz, points, bh0, bl0, b0, Gp);

    ballquery_kernel<<<BATCH*SPTS/8, 256>>>(xyz, new_xyz, gidx);

    y1build_kernel<<<MBLK, 256>>>(Gp, gidx, xyz, new_xyz, w0, y1, partSum, partSq);
    stats_kernel<<<CH1, 256>>>(partSum, partSq, CH1, g0, bt0, scale, shift);

    // layer 2: 64 -> 128, single fp16 B, 3 CTAs/SM
    gemm_mma<128, 128, 64, 64, 64, true, false, 3><<<dim3(1, MBLK), 256, SM2>>>(
        y1, bh1, b1, scale, shift, y2, partSum, partSq, nullptr, nullptr);
    stats_kernel<<<CH2, 256>>>(partSum, partSq, CH2, g1, bt1, scale, shift);

    // layer 3: 128 -> 256 as 2x BN=128 blocks, 3 CTAs/SM, fused min/max
    gemm_mma<128, 256, 128, 64, 128, false, true, 3><<<dim3(2, MBLK), 256, SMW>>>(
        y2, bh2, b2, scale, shift, nullptr, partSum, partSq, gmax, gmin);
    stats_kernel<<<CH3, 256>>>(partSum, partSq, CH3, g2, bt2, scale, shift);

    finalpool_kernel<<<BATCH*SPTS, 256>>>(gmax, gmin, scale, shift, new_points);
}

// round 17
// speedup vs baseline: 1.2234x; 1.0042x over previous
#include <cuda_runtime.h>
#include <cuda_fp16.h>
#include <math.h>
#include <stdint.h>

// ---------------- problem constants ----------------
#define BATCH 16
#define NPTS  4096
#define DFEAT 64
#define SPTS  1024
#define NSAMP 32
#define CH0   67
#define CH1   64
#define CH2   128
#define CH3   256
#define MTOT  (BATCH*SPTS*NSAMP)   // 524288
#define MBLK  (MTOT/128)           // 4096
#define RAD2  0.04f
#define BNEPS 1e-5f

typedef unsigned long long ull;

// ---------------- device scratch ----------------
__device__ float    g_G[(size_t)BATCH*NPTS*CH1];
__device__ uint32_t g_y1[(size_t)MTOT*CH1/2];      // fp16 pairs
__device__ uint32_t g_y2[(size_t)MTOT*CH2/2];      // fp16 pairs
__device__ float g_part[2*(size_t)MBLK*CH3];       // transposed [n][MBLK]
__device__ float g_scale[CH3];
__device__ float g_shift[CH3];
__device__ float g_gmax[(size_t)BATCH*SPTS*CH3];
__device__ float g_gmin[(size_t)BATCH*SPTS*CH3];
__device__ __half g_bh0[64*64],   g_bl0[64*64];
__device__ __half g_bh1[64*128],  g_bl1[64*128];
__device__ __half g_bh2[128*256], g_bl2[128*256];

// ---------------- helpers ----------------
__device__ __forceinline__ uint32_t smem_u32(const void* p) {
    uint32_t a;
    asm("{ .reg .u64 t; cvta.to.shared.u64 t, %1; cvt.u32.u64 %0, t; }" : "=r"(a) : "l"(p));
    return a;
}
__device__ __forceinline__ void ldsm4(uint32_t* r, uint32_t a) {
    asm volatile("ldmatrix.sync.aligned.m8n8.x4.shared.b16 {%0,%1,%2,%3}, [%4];"
                 : "=r"(r[0]), "=r"(r[1]), "=r"(r[2]), "=r"(r[3]) : "r"(a));
}
__device__ __forceinline__ void ldsm4t(uint32_t* r, uint32_t a) {
    asm volatile("ldmatrix.sync.aligned.m8n8.x4.trans.shared.b16 {%0,%1,%2,%3}, [%4];"
                 : "=r"(r[0]), "=r"(r[1]), "=r"(r[2]), "=r"(r[3]) : "r"(a));
}
__device__ __forceinline__ void mma_f16(float* c, const uint32_t* a, uint32_t b0, uint32_t b1) {
    asm volatile(
        "mma.sync.aligned.m16n8k16.row.col.f32.f16.f16.f32 "
        "{%0,%1,%2,%3}, {%4,%5,%6,%7}, {%8,%9}, {%0,%1,%2,%3};"
        : "+f"(c[0]), "+f"(c[1]), "+f"(c[2]), "+f"(c[3])
        : "r"(a[0]), "r"(a[1]), "r"(a[2]), "r"(a[3]), "r"(b0), "r"(b1));
}
__device__ __forceinline__ uint32_t packh2(float v0, float v1) {
    __half2 h = __floats2half2_rn(v0, v1);
    return *(uint32_t*)&h;
}

// ---------------- fused FPS + G-GEMM ----------------
// bid 0..15: FPS (one block per batch). bid 16..527: G = points.W0[3:67]+b0, mb=bid-16.
__global__ __launch_bounds__(512, 2) void fpsg_kernel(
    const float* __restrict__ xyz, float* __restrict__ new_xyz,
    const float* __restrict__ points,
    const __half* __restrict__ BH, const __half* __restrict__ BL,
    const float* __restrict__ bias,
    float* __restrict__ G)
{
    extern __shared__ __align__(16) char dyn[];
    const int tid = threadIdx.x;
    const int lane = tid & 31, wid = tid >> 5;

    if (blockIdx.x < 16) {
        // ================= FPS =================
        float* sx = (float*)dyn;
        float* sy = sx + NPTS;
        float* sz = sy + NPTS;
        __shared__ unsigned s_val[2][16], s_low[2][16];
        const int b = blockIdx.x;
        const float* X = xyz + (size_t)b * NPTS * 3;

        ull pxp[4], pyp[4], pzp[4];
        float dist[8];
#pragma unroll
        for (int t = 0; t < 8; t++) dist[t] = 1e10f;
#pragma unroll
        for (int t = 0; t < 4; t++) {
            const int j0 = tid + (2*t) * 512, j1 = tid + (2*t+1) * 512;
            float x0 = X[3*j0], y0 = X[3*j0+1], z0 = X[3*j0+2];
            float x1 = X[3*j1], y1 = X[3*j1+1], z1 = X[3*j1+2];
            sx[j0] = x0; sy[j0] = y0; sz[j0] = z0;
            sx[j1] = x1; sy[j1] = y1; sz[j1] = z1;
            asm("mov.b64 %0, {%1,%2};" : "=l"(pxp[t]) : "f"(x0), "f"(x1));
            asm("mov.b64 %0, {%1,%2};" : "=l"(pyp[t]) : "f"(y0), "f"(y1));
            asm("mov.b64 %0, {%1,%2};" : "=l"(pzp[t]) : "f"(z0), "f"(z1));
        }
        __syncthreads();

        int far = 0;
        for (int i = 0; i < SPTS; i++) {
            const float cx = sx[far], cy = sy[far], cz = sz[far];
            if (tid == 0) {
                float* o = new_xyz + ((size_t)b * SPTS + i) * 3;
                o[0] = cx; o[1] = cy; o[2] = cz;
            }
            if (i == SPTS - 1) break;

            const float mx = -cx, my = -cy, mz = -cz;
            ull ncx, ncy, ncz;
            asm("mov.b64 %0, {%1,%1};" : "=l"(ncx) : "f"(mx));
            asm("mov.b64 %0, {%1,%1};" : "=l"(ncy) : "f"(my));
            asm("mov.b64 %0, {%1,%1};" : "=l"(ncz) : "f"(mz));

            float bv = -1.0f; int bi = 0;
#pragma unroll
            for (int t = 0; t < 4; t++) {
                ull dx, dy, dz, dd;
                asm("add.rn.f32x2 %0, %1, %2;" : "=l"(dx) : "l"(pxp[t]), "l"(ncx));
                asm("add.rn.f32x2 %0, %1, %2;" : "=l"(dy) : "l"(pyp[t]), "l"(ncy));
                asm("add.rn.f32x2 %0, %1, %2;" : "=l"(dz) : "l"(pzp[t]), "l"(ncz));
                asm("mul.rn.f32x2 %0, %1, %2;" : "=l"(dd) : "l"(dx), "l"(dx));
                asm("fma.rn.f32x2 %0, %1, %2, %3;" : "=l"(dd) : "l"(dy), "l"(dy), "l"(dd));
                asm("fma.rn.f32x2 %0, %1, %2, %3;" : "=l"(dd) : "l"(dz), "l"(dz), "l"(dd));
                float d0, d1;
                asm("mov.b64 {%0,%1}, %2;" : "=f"(d0), "=f"(d1) : "l"(dd));
                const float nd0 = fminf(dist[2*t],   d0);
                const float nd1 = fminf(dist[2*t+1], d1);
                dist[2*t]   = nd0;
                dist[2*t+1] = nd1;
                if (nd0 > bv) { bv = nd0; bi = tid + (2*t)   * 512; }
                if (nd1 > bv) { bv = nd1; bi = tid + (2*t+1) * 512; }
            }
            const unsigned vb = __float_as_uint(bv);
            const unsigned m  = __reduce_max_sync(0xffffffffu, vb);
            const unsigned lw = __reduce_max_sync(0xffffffffu,
                                                  (vb == m) ? (0xFFFFu - (unsigned)bi) : 0u);
            const int buf = i & 1;
            if (lane == 0) { s_val[buf][wid] = m; s_low[buf][wid] = lw; }
            __syncthreads();

            const unsigned v2 = s_val[buf][lane & 15];
            const unsigned l2 = s_low[buf][lane & 15];
            const unsigned M  = __reduce_max_sync(0xffffffffu, v2);
            const unsigned LW = __reduce_max_sync(0xffffffffu, (v2 == M) ? l2 : 0u);
            far = 0xFFFF - (int)LW;
        }
        return;
    }

    // ================= G-GEMM (512 threads, 16 warps 4x4, B split) =================
    constexpr int BN = 64, K = 64;
    constexpr int LDA = K + 8, LDB = BN + 8;
    __half* aS  = (__half*)dyn;
    __half* bHi = aS + 128 * LDA;
    __half* bLo = bHi + K * LDB;

    const int mb = blockIdx.x - 16;
    const int m0 = mb * 128;
    const int wm = wid >> 2, wn = wid & 3;
    const int mW = wm * 32, nW = wn * 16;

    float acc[2][2][4];
#pragma unroll
    for (int i = 0; i < 2; i++)
#pragma unroll
        for (int j = 0; j < 2; j++)
#pragma unroll
            for (int q = 0; q < 4; q++) acc[i][j][q] = 0.f;

    for (int idx = tid; idx < 128 * (K/2); idx += 512) {
        const int r = idx / (K/2);
        const int kl = 2 * (idx - r * (K/2));
        const float2 f = *(const float2*)(points + (size_t)(m0 + r) * K + kl);
        *(uint32_t*)(aS + r * LDA + kl) = packh2(f.x, f.y);
    }
    for (int idx = tid; idx < K * (BN/2); idx += 512) {
        const int k = idx / (BN/2);
        const int n = 2 * (idx - k * (BN/2));
        *(uint32_t*)(bHi + k * LDB + n) = *(const uint32_t*)(BH + (size_t)k * BN + n);
        *(uint32_t*)(bLo + k * LDB + n) = *(const uint32_t*)(BL + (size_t)k * BN + n);
    }
    __syncthreads();

    const uint32_t aU   = smem_u32(aS)  + (uint32_t)(mW + (lane & 15)) * (LDA * 2) + (lane >> 4) * 16;
    const uint32_t bHiU = smem_u32(bHi) + (uint32_t)(lane & 15) * (LDB * 2) + (uint32_t)nW * 2 + (lane >> 4) * 16;
    const uint32_t bLoU = smem_u32(bLo) + (uint32_t)(lane & 15) * (LDB * 2) + (uint32_t)nW * 2 + (lane >> 4) * 16;

#pragma unroll
    for (int ks = 0; ks < K/16; ks++) {
        uint32_t a0[4], a1[4], bh[4], bl[4];
        ldsm4(a0, aU + ks * 32);
        ldsm4(a1, aU + 16 * LDA * 2 + ks * 32);
        const uint32_t bo = (uint32_t)ks * (16 * LDB * 2);
        ldsm4t(bh, bHiU + bo);
        ldsm4t(bl, bLoU + bo);
        mma_f16(acc[0][0], a0, bh[0], bh[1]);
        mma_f16(acc[0][1], a0, bh[2], bh[3]);
        mma_f16(acc[1][0], a1, bh[0], bh[1]);
        mma_f16(acc[1][1], a1, bh[2], bh[3]);
        mma_f16(acc[0][0], a0, bl[0], bl[1]);
        mma_f16(acc[0][1], a0, bl[2], bl[3]);
        mma_f16(acc[1][0], a1, bl[0], bl[1]);
        mma_f16(acc[1][1], a1, bl[2], bl[3]);
    }

    const int r0 = lane >> 2;
#pragma unroll
    for (int nt = 0; nt < 2; nt++) {
        const int colLocal = nW + nt * 8 + (lane & 3) * 2;
        const float b0v = __ldg(bias + colLocal);
        const float b1v = __ldg(bias + colLocal + 1);
        const size_t base = (size_t)(m0 + mW + r0) * BN + colLocal;
        *(float2*)(G + base)          = make_float2(acc[0][nt][0] + b0v, acc[0][nt][1] + b1v);
        *(float2*)(G + base +  8*BN)  = make_float2(acc[0][nt][2] + b0v, acc[0][nt][3] + b1v);
        *(float2*)(G + base + 16*BN)  = make_float2(acc[1][nt][0] + b0v, acc[1][nt][1] + b1v);
        *(float2*)(G + base + 24*BN)  = make_float2(acc[1][nt][2] + b0v, acc[1][nt][3] + b1v);
    }
}

// ---------------- unified weight prep (all 3 layers, bid-ranged) ----------------
__global__ __launch_bounds__(256) void prep_all_kernel(
    const float* __restrict__ W0, const float* __restrict__ W1, const float* __restrict__ W2,
    __half* __restrict__ bh0, __half* __restrict__ bl0,
    __half* __restrict__ bh1, __half* __restrict__ bl1,
    __half* __restrict__ bh2, __half* __restrict__ bl2)
{
    const int gi = blockIdx.x * 256 + threadIdx.x;
    // segment 0: W0 rows 3..66 -> [64][64], elems 4096
    // segment 1: W1 -> [64][128], elems 8192
    // segment 2: W2 -> [128][256], elems 32768
    if (gi < 4096) {
        const int k = gi >> 6, n = gi & 63;
        const float v = W0[(size_t)(k + 3) * 64 + n];
        __half h = __float2half_rn(v);
        bh0[gi] = h;
        bl0[gi] = __float2half_rn(v - __half2float(h));
    } else if (gi < 4096 + 8192) {
        const int i = gi - 4096;
        const float v = W1[i];
        __half h = __float2half_rn(v);
        bh1[i] = h;
        bl1[i] = __float2half_rn(v - __half2float(h));
    } else if (gi < 4096 + 8192 + 32768) {
        const int i = gi - 4096 - 8192;
        const float v = W2[i];
        __half h = __float2half_rn(v);
        bh2[i] = h;
        bl2[i] = __float2half_rn(v - __half2float(h));
    }
}

// ---------------- HMMA GEMM, 256 threads (layers 2 & 3) ----------------
template<int BN, int NTOT, int KPAD, int KC, int KORIG,
         bool STORE_Y, bool FMAX, int MINB>
__global__ void __launch_bounds__(256, MINB) gemm_mma(
    const uint32_t* __restrict__ A,
    const __half* __restrict__ BH,
    const float* __restrict__ bias,
    const float* __restrict__ scale, const float* __restrict__ shift,
    uint32_t* __restrict__ Y,
    float* __restrict__ partSum, float* __restrict__ partSq,
    float* __restrict__ gmax, float* __restrict__ gmin)
{
    extern __shared__ __align__(16) char dyn[];
    constexpr int LDA = KC + 8;
    constexpr int LDB = BN + 8;
    constexpr int NCHUNK = KPAD / KC;
    __half* aS  = (__half*)dyn;
    __half* bHi = aS + 128 * LDA;

    const int tid = threadIdx.x;
    const int nb = blockIdx.x, mb = blockIdx.y;
    const int m0 = mb * 128, n0 = nb * BN;

    const int wid = tid >> 5, lane = tid & 31;
    const int wm = wid >> 1, wn = wid & 1;
    const int mW = wm * 32, nW = wn * (BN / 2);
    constexpr int NT = BN / 16;
    constexpr int KSTEPS_C = KC / 16;

    float acc[2][NT][4];
#pragma unroll
    for (int i = 0; i < 2; i++)
#pragma unroll
        for (int j = 0; j < NT; j++)
#pragma unroll
            for (int q = 0; q < 4; q++) acc[i][j][q] = 0.f;

    const uint32_t aU   = smem_u32(aS)  + (uint32_t)(mW + (lane & 15)) * (LDA * 2) + (lane >> 4) * 16;
    const uint32_t bHiU = smem_u32(bHi) + (uint32_t)(lane & 15) * (LDB * 2) + (uint32_t)nW * 2 + (lane >> 4) * 16;

    for (int ch = 0; ch < NCHUNK; ch++) {
        const int kbase = ch * KC;
        if (ch > 0) __syncthreads();

        constexpr int AIT = 128 * (KC / 2);
        for (int idx = tid; idx < AIT; idx += 256) {
            const int r  = idx / (KC / 2);
            const int p  = idx - r * (KC / 2);
            const int kl = 2 * p;
            const int kk = kbase + kl;
            const uint32_t w = A[((size_t)(m0 + r) * KORIG + kk) >> 1];
            const float2 f = __half22float2(*(const __half2*)&w);
            float v0 = fmaxf(fmaf(f.x, __ldg(scale + kk),     __ldg(shift + kk)),     0.f);
            float v1 = fmaxf(fmaf(f.y, __ldg(scale + kk + 1), __ldg(shift + kk + 1)), 0.f);
            *(uint32_t*)(aS + r * LDA + kl) = packh2(v0, v1);
        }
        constexpr int BIT = KC * (BN / 2);
        for (int idx = tid; idx < BIT; idx += 256) {
            const int k = idx / (BN / 2);
            const int n = 2 * (idx - k * (BN / 2));
            *(uint32_t*)(bHi + k * LDB + n) = *(const uint32_t*)(BH + (size_t)(kbase + k) * NTOT + n0 + n);
        }
        __syncthreads();

#pragma unroll
        for (int ks = 0; ks < KSTEPS_C; ks++) {
            uint32_t a0[4], a1[4];
            ldsm4(a0, aU + ks * 32);
            ldsm4(a1, aU + 16 * LDA * 2 + ks * 32);
#pragma unroll
            for (int ng = 0; ng < NT / 2; ng++) {
                uint32_t bh[4];
                const uint32_t bo = (uint32_t)ks * (16 * LDB * 2) + ng * 32;
                ldsm4t(bh, bHiU + bo);
                mma_f16(acc[0][ng*2+0], a0, bh[0], bh[1]);
                mma_f16(acc[0][ng*2+1], a0, bh[2], bh[3]);
                mma_f16(acc[1][ng*2+0], a1, bh[0], bh[1]);
                mma_f16(acc[1][ng*2+1], a1, bh[2], bh[3]);
            }
        }
    }
    __syncthreads();

    float* sSum = (float*)dyn;            // [4][BN]
    float* sSq  = sSum + 4 * BN;

    const int r0 = lane >> 2;
#pragma unroll
    for (int nt = 0; nt < NT; nt++) {
        const int colLocal = nW + nt * 8 + (lane & 3) * 2;
        const float b0 = __ldg(bias + n0 + colLocal);
        const float b1 = __ldg(bias + n0 + colLocal + 1);
        float v0 = acc[0][nt][0] + b0, v1 = acc[0][nt][1] + b1;
        float v2 = acc[0][nt][2] + b0, v3 = acc[0][nt][3] + b1;
        float v4 = acc[1][nt][0] + b0, v5 = acc[1][nt][1] + b1;
        float v6 = acc[1][nt][2] + b0, v7 = acc[1][nt][3] + b1;
        if (STORE_Y) {
            const size_t base = ((size_t)(m0 + mW + r0) * NTOT + n0 + colLocal) >> 1;
            const size_t rstep = (size_t)8 * NTOT >> 1;
            Y[base]             = packh2(v0, v1);
            Y[base +     rstep] = packh2(v2, v3);
            Y[base + 2 * rstep] = packh2(v4, v5);
            Y[base + 3 * rstep] = packh2(v6, v7);
        }
        float s0 = v0+v2+v4+v6,              s1 = v1+v3+v5+v7;
        float q0 = v0*v0+v2*v2+v4*v4+v6*v6,  q1 = v1*v1+v3*v3+v5*v5+v7*v7;
        float mx0, mx1, mn0, mn1;
        if (FMAX) {
            mx0 = fmaxf(fmaxf(v0,v2), fmaxf(v4,v6)); mx1 = fmaxf(fmaxf(v1,v3), fmaxf(v5,v7));
            mn0 = fminf(fminf(v0,v2), fminf(v4,v6)); mn1 = fminf(fminf(v1,v3), fminf(v5,v7));
        }
#pragma unroll
        for (int d = 4; d < 32; d <<= 1) {
            s0 += __shfl_xor_sync(0xffffffffu, s0, d);
            s1 += __shfl_xor_sync(0xffffffffu, s1, d);
            q0 += __shfl_xor_sync(0xffffffffu, q0, d);
            q1 += __shfl_xor_sync(0xffffffffu, q1, d);
            if (FMAX) {
                mx0 = fmaxf(mx0, __shfl_xor_sync(0xffffffffu, mx0, d));
                mx1 = fmaxf(mx1, __shfl_xor_sync(0xffffffffu, mx1, d));
                mn0 = fminf(mn0, __shfl_xor_sync(0xffffffffu, mn0, d));
                mn1 = fminf(mn1, __shfl_xor_sync(0xffffffffu, mn1, d));
            }
        }
        if (lane < 4) {
            sSum[wm*BN + colLocal] = s0;  sSum[wm*BN + colLocal + 1] = s1;
            sSq [wm*BN + colLocal] = q0;  sSq [wm*BN + colLocal + 1] = q1;
            if (FMAX) {
                const size_t grp = (size_t)(mb * 4 + wm) * CH3 + n0 + colLocal;
                gmax[grp]     = mx0;  gmax[grp + 1] = mx1;
                gmin[grp]     = mn0;  gmin[grp + 1] = mn1;
            }
        }
    }
    __syncthreads();
    for (int n = tid; n < BN; n += 256) {
        float s = sSum[n] + sSum[BN + n] + sSum[2*BN + n] + sSum[3*BN + n];
        float q = sSq [n] + sSq [BN + n] + sSq [2*BN + n] + sSq [3*BN + n];
        partSum[(size_t)(n0 + n) * MBLK + mb] = s;
        partSq [(size_t)(n0 + n) * MBLK + mb] = q;
    }
}

// ---------------- y1build + fused ball query ----------------
// 8 warps, 4 centroids: warps 2c, 2c+1 scan halves [0,2048) and [2048,4096) for
// centroid c with the exact ballot-rank collection, then merge first-32 ascending.
__global__ __launch_bounds__(256) void y1build_kernel(
    const float* __restrict__ G,
    const float* __restrict__ xyz, const float* __restrict__ nxyz,
    const float* __restrict__ w0,
    uint32_t* __restrict__ y1,
    float* __restrict__ partSum, float* __restrict__ partSq)
{
    __shared__ int   sIdx[128];
    __shared__ int   sBuf[8][32];
    __shared__ int   sCnt[8], sFirst[8], sHas[8];
    __shared__ float sCen[12];
    __shared__ float sW[192];
    __shared__ float sXn[128*3];
    __shared__ float sRed[1024];
    const int mb = blockIdx.x, m0 = mb * 128, tid = threadIdx.x;
    const int b = mb >> 8;
    const int lane = tid & 31, wid = tid >> 5;

    if (tid < 12)  sCen[tid] = nxyz[(size_t)(mb * 4) * 3 + tid];
    if (tid < 192) sW[tid]   = w0[tid];
    if (tid < 8)   { sCnt[tid] = 0; sFirst[tid] = 0; sHas[tid] = 0; }
    __syncthreads();

    // ---- fused ball query: warp wid handles centroid (wid>>1), half (wid&1) ----
    {
        const int cid  = wid >> 1;
        const int half = wid & 1;
        const float cx = sCen[cid*3+0];
        const float cy = sCen[cid*3+1];
        const float cz = sCen[cid*3+2];
        const float ss = cx*cx + cy*cy + cz*cz;
        const float* X = xyz + (size_t)b * NPTS * 3;
        const int baseLo = half * 2048, baseHi = baseLo + 2048;

        int cnt = 0, firstIdx = 0, has = 0;
        for (int base = baseLo; base < baseHi && cnt < NSAMP; base += 32) {
            const int j = base + lane;
            const float x = X[3*j], y = X[3*j+1], z = X[3*j+2];
            const float pp  = x*x + y*y + z*z;
            const float dot = x*cx + y*cy + z*cz;
            const float d   = (-2.0f*dot + ss) + pp;
            const bool  in  = !(d > RAD2);
            unsigned mask = __ballot_sync(0xffffffffu, in);
            if (cnt == 0 && mask) { firstIdx = base + (__ffs(mask) - 1); has = 1; }
            int rank = __popc(mask & ((1u << lane) - 1u));
            int slot = cnt + rank;
            if (in && slot < NSAMP) sBuf[wid][slot] = j;
            cnt += __popc(mask);
        }
        if (lane == 0) {
            sCnt[wid]   = cnt < NSAMP ? cnt : NSAMP;
            sFirst[wid] = firstIdx;
            sHas[wid]   = has;
        }
    }
    __syncthreads();

    // ---- merge halves: first 32 of (halfA ++ halfB), pad with overall-first ----
    if (tid < 128) {
        const int c = tid >> 5, k = tid & 31;
        const int cA = sCnt[2*c], cB = sCnt[2*c+1];
        const int fi = sHas[2*c] ? sFirst[2*c] : sFirst[2*c+1];
        int v;
        if (k < cA)            v = sBuf[2*c][k];
        else if (k - cA < cB)  v = sBuf[2*c+1][k - cA];
        else                   v = fi;
        sIdx[tid] = v;
    }
    __syncthreads();
    if (tid < 128) {
        const int g = tid >> 5;
        const int j = sIdx[tid];
        const float* xp = xyz + ((size_t)b * NPTS + j) * 3;
        sXn[tid*3+0] = xp[0] - sCen[g*3+0];
        sXn[tid*3+1] = xp[1] - sCen[g*3+1];
        sXn[tid*3+2] = xp[2] - sCen[g*3+2];
    }
    __syncthreads();

    const int cp = tid & 31;
    const int rg = tid >> 5;
    const int c0 = 2 * cp;
    const float wx0 = sW[c0],   wy0 = sW[64+c0],   wz0 = sW[128+c0];
    const float wx1 = sW[c0+1], wy1 = sW[64+c0+1], wz1 = sW[128+c0+1];

    float s0 = 0.f, s1 = 0.f, q0 = 0.f, q1 = 0.f;
#pragma unroll 4
    for (int rr = 0; rr < 16; rr++) {
        const int r = rg * 16 + rr;
        const int j = sIdx[r];
        const float xn = sXn[r*3], yn = sXn[r*3+1], zn = sXn[r*3+2];
        const float2 gv = *(const float2*)(G + ((size_t)b * NPTS + j) * CH1 + c0);
        float v0 = fmaf(zn, wz0, fmaf(yn, wy0, fmaf(xn, wx0, gv.x)));
        float v1 = fmaf(zn, wz1, fmaf(yn, wy1, fmaf(xn, wx1, gv.y)));
        y1[(size_t)(m0 + r) * (CH1/2) + cp] = packh2(v0, v1);
        s0 += v0; s1 += v1; q0 += v0*v0; q1 += v1*v1;
    }
    sRed[rg*64 + c0]       = s0;  sRed[rg*64 + c0 + 1]       = s1;
    sRed[512 + rg*64 + c0] = q0;  sRed[512 + rg*64 + c0 + 1] = q1;
    __syncthreads();
    if (rg == 0) {
        float S0 = 0.f, S1 = 0.f, Q0 = 0.f, Q1 = 0.f;
#pragma unroll
        for (int g2 = 0; g2 < 8; g2++) {
            S0 += sRed[g2*64 + c0];       S1 += sRed[g2*64 + c0 + 1];
            Q0 += sRed[512 + g2*64 + c0]; Q1 += sRed[512 + g2*64 + c0 + 1];
        }
        partSum[(size_t)c0 * MBLK + mb]       = S0;
        partSum[(size_t)(c0 + 1) * MBLK + mb] = S1;
        partSq [(size_t)c0 * MBLK + mb]       = Q0;
        partSq [(size_t)(c0 + 1) * MBLK + mb] = Q1;
    }
}

// ---------------- fold partials -> scale/shift ----------------
__global__ __launch_bounds__(256) void stats_kernel(const float* __restrict__ partSum,
                                                    const float* __restrict__ partSq,
                                                    int N,
                                                    const float* __restrict__ g,
                                                    const float* __restrict__ bt,
                                                    float* __restrict__ scale,
                                                    float* __restrict__ shift)
{
    const int c = blockIdx.x, tid = threadIdx.x;
    __shared__ float ss[256], sq[256];
    float a = 0.f, b2 = 0.f;
    const float* ps = partSum + (size_t)c * MBLK;
    const float* pq = partSq  + (size_t)c * MBLK;
    for (int mb = tid; mb < MBLK; mb += 256) {
        a  += ps[mb];
        b2 += pq[mb];
    }
    ss[tid] = a; sq[tid] = b2;
    __syncthreads();
    for (int s = 128; s > 0; s >>= 1) {
        if (tid < s) { ss[tid] += ss[tid+s]; sq[tid] += sq[tid+s]; }
        __syncthreads();
    }
    if (tid == 0) {
        const float invM = 1.0f / (float)MTOT;
        float mean = ss[0] * invM;
        float var  = sq[0] * invM - mean * mean;
        float sc   = g[c] / sqrtf(var + BNEPS);
        scale[c] = sc;
        shift[c] = bt[c] - mean * sc;
    }
}

// ---------------- final pool ----------------
__global__ __launch_bounds__(256) void finalpool_kernel(const float* __restrict__ gmax,
                                                        const float* __restrict__ gmin,
                                                        const float* __restrict__ scale,
                                                        const float* __restrict__ shift,
                                                        float* __restrict__ out)
{
    const int g = blockIdx.x, c = threadIdx.x;
    const float sc = scale[c], sh = shift[c];
    const float v = (sc >= 0.f) ? gmax[(size_t)g * CH3 + c] : gmin[(size_t)g * CH3 + c];
    out[(size_t)g * CH3 + c] = fmaxf(fmaf(v, sc, sh), 0.f);
}

// ---------------- launch ----------------
extern "C" void kernel_launch(void* const* d_in, const int* in_sizes, int n_in,
                              void* d_out, int out_size)
{
    const float* xyz    = (const float*)d_in[0];
    const float* points = (const float*)d_in[1];
    const float* w0  = (const float*)d_in[2];
    const float* b0  = (const float*)d_in[3];
    const float* g0  = (const float*)d_in[4];
    const float* bt0 = (const float*)d_in[5];
    const float* w1  = (const float*)d_in[6];
    const float* b1  = (const float*)d_in[7];
    const float* g1  = (const float*)d_in[8];
    const float* bt1 = (const float*)d_in[9];
    const float* w2  = (const float*)d_in[10];
    const float* b2  = (const float*)d_in[11];
    const float* g2  = (const float*)d_in[12];
    const float* bt2 = (const float*)d_in[13];

    float* out        = (float*)d_out;
    float* new_xyz    = out;
    float* new_points = out + (size_t)BATCH*SPTS*3;

    float *Gp, *part, *scale, *shift, *gmax, *gmin;
    uint32_t *y1, *y2;
    __half *bh0, *bl0, *bh1, *bl1, *bh2, *bl2;
    cudaGetSymbolAddress((void**)&Gp,    g_G);
    cudaGetSymbolAddress((void**)&y1,    g_y1);
    cudaGetSymbolAddress((void**)&y2,    g_y2);
    cudaGetSymbolAddress((void**)&part,  g_part);
    cudaGetSymbolAddress((void**)&scale, g_scale);
    cudaGetSymbolAddress((void**)&shift, g_shift);
    cudaGetSymbolAddress((void**)&gmax,  g_gmax);
    cudaGetSymbolAddress((void**)&gmin,  g_gmin);
    cudaGetSymbolAddress((void**)&bh0,   g_bh0);
    cudaGetSymbolAddress((void**)&bl0,   g_bl0);
    cudaGetSymbolAddress((void**)&bh1,   g_bh1);
    cudaGetSymbolAddress((void**)&bl1,   g_bl1);
    cudaGetSymbolAddress((void**)&bh2,   g_bh2);
    cudaGetSymbolAddress((void**)&bl2,   g_bl2);

    float* partSum = part;
    float* partSq  = part + (size_t)MBLK * CH3;

    constexpr int SMF = 3 * NPTS * 4;                    // 49,152 (FPS cache; G fits inside)
    constexpr int SM2 = (128*(64+8) + 64*(128+8)) * 2;   // 35,840
    constexpr int SMW = SM2;

    static bool attrDone = false;
    if (!attrDone) {
        cudaFuncSetAttribute(fpsg_kernel,
                             cudaFuncAttributeMaxDynamicSharedMemorySize, SMF);
        cudaFuncSetAttribute(gemm_mma<128, 128, 64, 64, 64, true, false, 3>,
                             cudaFuncAttributeMaxDynamicSharedMemorySize, SM2);
        cudaFuncSetAttribute(gemm_mma<128, 256, 128, 64, 128, false, true, 3>,
                             cudaFuncAttributeMaxDynamicSharedMemorySize, SMW);
        attrDone = true;
    }

    // one prep kernel for all three weight matrices
    prep_all_kernel<<<(4096 + 8192 + 32768 + 255)/256, 256>>>(
        w0, w1, w2, bh0, bl0, bh1, bl1, bh2, bl2);

    // fused: FPS (16 CTAs) + G-GEMM (512 CTAs) run concurrently
    fpsg_kernel<<<16 + 512, 512, SMF>>>(xyz, new_xyz, points, bh0, bl0, b0, Gp);

    // layer 1 with fused ball query (no gidx round-trip)
    y1build_kernel<<<MBLK, 256>>>(Gp, xyz, new_xyz, w0, y1, partSum, partSq);
    stats_kernel<<<CH1, 256>>>(partSum, partSq, CH1, g0, bt0, scale, shift);

    // layer 2: 64 -> 128, single fp16 B, 3 CTAs/SM
    gemm_mma<128, 128, 64, 64, 64, true, false, 3><<<dim3(1, MBLK), 256, SM2>>>(
        y1, bh1, b1, scale, shift, y2, partSum, partSq, nullptr, nullptr);
    stats_kernel<<<CH2, 256>>>(partSum, partSq, CH2, g1, bt1, scale, shift);

    // layer 3: 128 -> 256 as 2x BN=128 blocks, 3 CTAs/SM, fused min/max
    gemm_mma<128, 256, 128, 64, 128, false, true, 3><<<dim3(2, MBLK), 256, SMW>>>(
        y2, bh2, b2, scale, shift, nullptr, partSum, partSq, gmax, gmin);
    stats_kernel<<<CH3, 256>>>(partSum, partSq, CH3, g2, bt2, scale, shift);

    finalpool_kernel<<<BATCH*SPTS, 256>>>(gmax, gmin, scale, shift, new_points);
}